// round 10
// baseline (speedup 1.0000x reference)
#include <cuda_runtime.h>
#include <cuda_bf16.h>
#include <math.h>

#define B_  64
#define C_  128
#define S_  1024
#define EPS 1e-6f
#define SCALE_ 0.044194173824159216f
#define LOG2E_ 1.4426950408889634f

typedef __nv_bfloat16 bf16;

// ---------------- scratch (device globals) ----------------
__device__ bf16 g_t[(size_t)B_ * S_ * C_];
__device__ unsigned char g_q8[(size_t)B_ * S_ * C_];   // Q in e4m3 (scale*log2e folded in)
__device__ unsigned char g_k8[(size_t)B_ * S_ * C_];   // K in e4m3
__device__ bf16 g_v[(size_t)B_ * S_ * C_];
__device__ bf16 g_o[(size_t)B_ * S_ * C_];
__device__ bf16 g_wb[4 * 16384];

// ---------------- helpers ----------------
__device__ __forceinline__ unsigned pack2(float a, float b) {
    __nv_bfloat162 h = __floats2bfloat162_rn(a, b);
    return *reinterpret_cast<unsigned*>(&h);
}
__device__ __forceinline__ unsigned short pk8(float lo, float hi) {
    unsigned short r;
    asm("cvt.rn.satfinite.e4m3x2.f32 %0, %1, %2;" : "=h"(r) : "f"(hi), "f"(lo));
    return r;
}
__device__ __forceinline__ float ex2(float x) {
    float r; asm("ex2.approx.ftz.f32 %0, %1;" : "=f"(r) : "f"(x)); return r;
}
__device__ __forceinline__ void mma_bf16(float* d, const unsigned* a, unsigned b0, unsigned b1) {
    asm volatile(
        "mma.sync.aligned.m16n8k16.row.col.f32.bf16.bf16.f32 "
        "{%0,%1,%2,%3}, {%4,%5,%6,%7}, {%8,%9}, {%0,%1,%2,%3};\n"
        : "+f"(d[0]), "+f"(d[1]), "+f"(d[2]), "+f"(d[3])
        : "r"(a[0]), "r"(a[1]), "r"(a[2]), "r"(a[3]), "r"(b0), "r"(b1));
}
__device__ __forceinline__ void mma_fp8(float* d, const unsigned* a, unsigned b0, unsigned b1) {
    asm volatile(
        "mma.sync.aligned.m16n8k32.row.col.f32.e4m3.e4m3.f32 "
        "{%0,%1,%2,%3}, {%4,%5,%6,%7}, {%8,%9}, {%0,%1,%2,%3};\n"
        : "+f"(d[0]), "+f"(d[1]), "+f"(d[2]), "+f"(d[3])
        : "r"(a[0]), "r"(a[1]), "r"(a[2]), "r"(a[3]), "r"(b0), "r"(b1));
}
__device__ __forceinline__ void ldm_x4(unsigned* r, unsigned addr) {
    asm volatile("ldmatrix.sync.aligned.m8n8.x4.shared.b16 {%0,%1,%2,%3}, [%4];"
                 : "=r"(r[0]), "=r"(r[1]), "=r"(r[2]), "=r"(r[3]) : "r"(addr));
}
__device__ __forceinline__ void ldm_x4t(unsigned* r, unsigned addr) {
    asm volatile("ldmatrix.sync.aligned.m8n8.x4.trans.shared.b16 {%0,%1,%2,%3}, [%4];"
                 : "=r"(r[0]), "=r"(r[1]), "=r"(r[2]), "=r"(r[3]) : "r"(addr));
}
__device__ __forceinline__ unsigned cvta_s(const void* p) {
    return (unsigned)__cvta_generic_to_shared(p);
}
#define CP16(dst, src) asm volatile("cp.async.cg.shared.global [%0], [%1], 16;" :: "r"(dst), "l"(src))
#define CP_COMMIT() asm volatile("cp.async.commit_group;")

#define TILE_BYTES 34816   // 128 * 272 (bf16 tiles)
#define KV_BYTES   17408   // 64 * 272 (bf16 V tile)
#define K8_BYTES   9216    // 64 * 144 (fp8 tile)

// ---------------- Kernel 0: convert weights fp32 -> bf16 ----------------
__global__ void convw_kernel(const float* __restrict__ wq, const float* __restrict__ wk,
                             const float* __restrict__ wv, const float* __restrict__ wo,
                             bf16* __restrict__ dst) {
    int i = blockIdx.x * 256 + threadIdx.x;
    const float* s;
    int m = i >> 12;
    if (m == 0) s = wq; else if (m == 1) s = wk; else if (m == 2) s = wv; else s = wo;
    float4 v = reinterpret_cast<const float4*>(s)[i & 4095];
    uint2 u; u.x = pack2(v.x, v.y); u.y = pack2(v.z, v.w);
    reinterpret_cast<uint2*>(dst)[i] = u;
}

// ---------------- Kernel 1: GroupNorm -> t[b,s,c] (bf16) ----------------
__global__ void gn_kernel(const float* __restrict__ x, const float* __restrict__ gw,
                          const float* __restrict__ gb, bf16* __restrict__ t) {
    int b = blockIdx.x >> 5, g = blockIdx.x & 31, tid = threadIdx.x;
    const float* xb = x + ((size_t)b * C_ + g * 4) * S_;
    float vals[4][4], s1 = 0.f, s2 = 0.f;
#pragma unroll
    for (int it = 0; it < 4; ++it) {
        int s = tid + it * 256;
#pragma unroll
        for (int j = 0; j < 4; ++j) {
            float v = xb[(size_t)j * S_ + s];
            vals[it][j] = v; s1 += v; s2 += v * v;
        }
    }
    __shared__ float red0[256], red1[256];
    red0[tid] = s1; red1[tid] = s2;
    __syncthreads();
    for (int off = 128; off > 0; off >>= 1) {
        if (tid < off) { red0[tid] += red0[tid + off]; red1[tid] += red1[tid + off]; }
        __syncthreads();
    }
    __shared__ float mean_s, inv_s;
    if (tid == 0) {
        float m = red0[0] * (1.f / 4096.f);
        float var = red1[0] * (1.f / 4096.f) - m * m;
        mean_s = m; inv_s = rsqrtf(var + EPS);
    }
    __syncthreads();
    float m = mean_s, inv = inv_s, w4[4], b4[4];
#pragma unroll
    for (int j = 0; j < 4; ++j) { w4[j] = gw[g * 4 + j]; b4[j] = gb[g * 4 + j]; }
#pragma unroll
    for (int it = 0; it < 4; ++it) {
        int s = tid + it * 256;
        uint2 u;
        u.x = pack2((vals[it][0] - m) * inv * w4[0] + b4[0], (vals[it][1] - m) * inv * w4[1] + b4[1]);
        u.y = pack2((vals[it][2] - m) * inv * w4[2] + b4[2], (vals[it][3] - m) * inv * w4[3] + b4[3]);
        *reinterpret_cast<uint2*>(&t[((size_t)b * S_ + s) * C_ + g * 4]) = u;
    }
}

// ---------------- Kernel 2: fused QKV projection (bf16 mma; q,k stored fp8) ----------------
#define QKV_SMEM (4 * TILE_BYTES)
__global__ __launch_bounds__(256, 1) void qkv_kernel(
    const bf16* __restrict__ t, const bf16* __restrict__ wb,
    const float* __restrict__ bq, const float* __restrict__ bk, const float* __restrict__ bv,
    unsigned char* __restrict__ q8, unsigned char* __restrict__ k8, bf16* __restrict__ v) {
    extern __shared__ char sm[];
    unsigned sb = cvta_s(sm);
    int tid = threadIdx.x, lane = tid & 31, w = tid >> 5;
    int g = lane >> 2, tt = lane & 3, lm = lane >> 3, lr = lane & 7;
    size_t m0 = (size_t)blockIdx.x * 128;

    for (int i = tid; i < 2048; i += 256) {
        int row = i >> 4, seg = i & 15;
        CP16(sb + row * 272 + seg * 16, t + (m0 + row) * 128 + seg * 8);
    }
#pragma unroll
    for (int wi = 0; wi < 3; ++wi)
        for (int i = tid; i < 2048; i += 256) {
            int row = i >> 4, seg = i & 15;
            CP16(sb + (wi + 1) * TILE_BYTES + row * 272 + seg * 16,
                 wb + wi * 16384 + row * 128 + seg * 8);
        }
    CP_COMMIT();
    asm volatile("cp.async.wait_group 0;");
    __syncthreads();

    int wm = (w >> 1) * 32, wn = (w & 1) * 64;
    unsigned af[2][8][4];
#pragma unroll
    for (int mi = 0; mi < 2; ++mi)
#pragma unroll
        for (int kk = 0; kk < 8; ++kk) {
            unsigned addr = sb + (unsigned)(wm + 16 * mi + 8 * (lm & 1) + lr) * 272
                          + (unsigned)(kk * 32 + (lm >> 1) * 16);
            ldm_x4(af[mi][kk], addr);
        }

    const float* Bs[3] = {bq, bk, bv};
#pragma unroll 1
    for (int wi = 0; wi < 3; ++wi) {
        unsigned swb = sb + (wi + 1) * TILE_BYTES;
        float acc[2][8][4];
#pragma unroll
        for (int mi = 0; mi < 2; ++mi)
#pragma unroll
            for (int j = 0; j < 8; ++j)
#pragma unroll
                for (int r = 0; r < 4; ++r) acc[mi][j][r] = 0.f;
#pragma unroll
        for (int kk = 0; kk < 8; ++kk)
#pragma unroll
            for (int jp = 0; jp < 4; ++jp) {
                unsigned kb[4];
                unsigned addr = swb + (unsigned)(wn + 16 * jp + 8 * (lm >> 1) + lr) * 272
                              + (unsigned)(kk * 32 + (lm & 1) * 16);
                ldm_x4(kb, addr);
                mma_bf16(acc[0][2 * jp], af[0][kk], kb[0], kb[1]);
                mma_bf16(acc[0][2 * jp + 1], af[0][kk], kb[2], kb[3]);
                mma_bf16(acc[1][2 * jp], af[1][kk], kb[0], kb[1]);
                mma_bf16(acc[1][2 * jp + 1], af[1][kk], kb[2], kb[3]);
            }
        const float* bias = Bs[wi];
        if (wi < 2) {
            unsigned char* Out8 = (wi == 0) ? q8 : k8;
            float sc = (wi == 0) ? (SCALE_ * LOG2E_) : 1.f;
#pragma unroll
            for (int mi = 0; mi < 2; ++mi) {
                int r = wm + 16 * mi + g;
#pragma unroll
                for (int j = 0; j < 8; ++j) {
                    int col = wn + 8 * j + 2 * tt;
                    float b0f = bias[col], b1f = bias[col + 1];
                    *reinterpret_cast<unsigned short*>(Out8 + (m0 + r) * 128 + col) =
                        pk8((acc[mi][j][0] + b0f) * sc, (acc[mi][j][1] + b1f) * sc);
                    *reinterpret_cast<unsigned short*>(Out8 + (m0 + r + 8) * 128 + col) =
                        pk8((acc[mi][j][2] + b0f) * sc, (acc[mi][j][3] + b1f) * sc);
                }
            }
        } else {
#pragma unroll
            for (int mi = 0; mi < 2; ++mi) {
                int r = wm + 16 * mi + g;
#pragma unroll
                for (int j = 0; j < 8; ++j) {
                    int col = wn + 8 * j + 2 * tt;
                    float b0f = bias[col], b1f = bias[col + 1];
                    *reinterpret_cast<unsigned*>(v + (m0 + r) * 128 + col) =
                        pack2(acc[mi][j][0] + b0f, acc[mi][j][1] + b1f);
                    *reinterpret_cast<unsigned*>(v + (m0 + r + 8) * 128 + col) =
                        pack2(acc[mi][j][2] + b0f, acc[mi][j][3] + b1f);
                }
            }
        }
    }
}

// ---------------- Kernel 3: flash attention — R6 structure, fp8 QK^T, bf16 PV ----------------
// 128 threads, 64 Q rows (16/warp), 2 CTAs/SM.
// smem: Q8 [64 x 144B], K8 double [64 x 144B] x2, V double [64 x 272B] x2 = 62464 B
#define ATT_Q8_BYTES 9216
#define ATT_K8_OFF   ATT_Q8_BYTES
#define ATT_V_OFF    (ATT_Q8_BYTES + 2 * K8_BYTES)
#define ATT_SMEM     (ATT_V_OFF + 2 * KV_BYTES)
__global__ __launch_bounds__(128, 2) void attn_kernel(
    const unsigned char* __restrict__ Q8, const unsigned char* __restrict__ K8,
    const bf16* __restrict__ V, bf16* __restrict__ O) {
    extern __shared__ char sm[];
    unsigned sb = cvta_s(sm);
    int tid = threadIdx.x, lane = tid & 31, w = tid >> 5;
    int g = lane >> 2, tt = lane & 3;
    int lm = lane >> 3, lr = lane & 7;
    int b = blockIdx.x >> 4, qt = blockIdx.x & 15;
    size_t base = (size_t)b * S_ * C_;
    int q0 = qt * 64;
    int r0 = w * 16 + g;

    // prologue: Q8 (64 x 128B) + K8 block0 + V block0
    for (int i = tid; i < 512; i += 128) {
        int row = i >> 3, seg = i & 7;
        CP16(sb + row * 144 + seg * 16, Q8 + base + (size_t)(q0 + row) * 128 + seg * 16);
        CP16(sb + ATT_K8_OFF + row * 144 + seg * 16, K8 + base + (size_t)row * 128 + seg * 16);
    }
    for (int i = tid; i < 1024; i += 128) {
        int row = i >> 4, seg = i & 15;
        CP16(sb + ATT_V_OFF + row * 272 + seg * 16, V + base + (size_t)row * 128 + seg * 8);
    }
    CP_COMMIT();
    asm volatile("cp.async.wait_group 0;");
    __syncthreads();

    // Q fragments (fp8 m16n8k32, 4 k-steps); warp w covers rows [16w, 16w+16)
    unsigned qa[4][4];
#pragma unroll
    for (int kk = 0; kk < 4; ++kk) {
        unsigned addr = sb + (unsigned)(w * 16 + 8 * (lm & 1) + lr) * 144
                      + (unsigned)(kk * 32 + (lm >> 1) * 16);
        ldm_x4(qa[kk], addr);
    }

    float o_[16][4];
#pragma unroll
    for (int j = 0; j < 16; ++j)
#pragma unroll
        for (int r = 0; r < 4; ++r) o_[j][r] = 0.f;
    float l0 = 0.f, l1 = 0.f;

    CP_COMMIT();   // empty group for uniform wait depth

    for (int kt = 0; kt < 16; ++kt) {
        int cur = kt & 1;
        asm volatile("cp.async.wait_group 0;");
        __syncthreads();

        // prefetch next K8/V into other buffer
        if (kt < 15) {
            unsigned kdst = sb + ATT_K8_OFF + (1 - cur) * K8_BYTES;
            unsigned vdst = sb + ATT_V_OFF + (1 - cur) * KV_BYTES;
            const unsigned char* ksrc = K8 + base + (size_t)(kt + 1) * 64 * 128;
            const bf16* vsrc = V + base + (size_t)(kt + 1) * 64 * 128;
            for (int i = tid; i < 512; i += 128) {
                int row = i >> 3, seg = i & 7;
                CP16(kdst + row * 144 + seg * 16, ksrc + (size_t)row * 128 + seg * 16);
            }
            for (int i = tid; i < 1024; i += 128) {
                int row = i >> 4, seg = i & 15;
                CP16(vdst + row * 272 + seg * 16, vsrc + (size_t)row * 128 + seg * 8);
            }
        }
        CP_COMMIT();

        unsigned skb = sb + ATT_K8_OFF + cur * K8_BYTES;
        unsigned svb = sb + ATT_V_OFF + cur * KV_BYTES;

        // ---- S = Q . K^T (16 x 64 per warp, fp8 k32) ----
        float s[8][4];
#pragma unroll
        for (int j = 0; j < 8; ++j)
#pragma unroll
            for (int r = 0; r < 4; ++r) s[j][r] = 0.f;
#pragma unroll
        for (int kk = 0; kk < 4; ++kk)
#pragma unroll
            for (int jp = 0; jp < 4; ++jp) {
                unsigned kb[4];
                unsigned addr = skb + (unsigned)(16 * jp + 8 * (lm >> 1) + lr) * 144
                              + (unsigned)(kk * 32 + (lm & 1) * 16);
                ldm_x4(kb, addr);
                mma_fp8(s[2 * jp], qa[kk], kb[0], kb[1]);
                mma_fp8(s[2 * jp + 1], qa[kk], kb[2], kb[3]);
            }

        // ---- softmax numerator (no max shift; logits tiny by construction) ----
        unsigned pa[4][4];
#pragma unroll
        for (int j = 0; j < 8; ++j) {
            float p00 = ex2(s[j][0]), p01 = ex2(s[j][1]);
            float p10 = ex2(s[j][2]), p11 = ex2(s[j][3]);
            l0 += p00 + p01; l1 += p10 + p11;
            pa[j >> 1][(j & 1) * 2 + 0] = pack2(p00, p01);
            pa[j >> 1][(j & 1) * 2 + 1] = pack2(p10, p11);
        }

        // ---- O += P . V via ldmatrix.x4.trans (bf16) ----
#pragma unroll
        for (int kt2 = 0; kt2 < 4; ++kt2) {
#pragma unroll
            for (int jp = 0; jp < 8; ++jp) {
                unsigned vb[4];
                unsigned addr = svb + (unsigned)(kt2 * 16 + 8 * (lm & 1) + lr) * 272
                              + (unsigned)((2 * jp + (lm >> 1)) * 16);
                ldm_x4t(vb, addr);
                mma_bf16(o_[2 * jp], pa[kt2], vb[0], vb[1]);
                mma_bf16(o_[2 * jp + 1], pa[kt2], vb[2], vb[3]);
            }
        }
    }

    // final row-sum reduction + store
    l0 += __shfl_xor_sync(0xffffffffu, l0, 1);
    l0 += __shfl_xor_sync(0xffffffffu, l0, 2);
    l1 += __shfl_xor_sync(0xffffffffu, l1, 1);
    l1 += __shfl_xor_sync(0xffffffffu, l1, 2);
    float i0 = 1.f / l0, i1 = 1.f / l1;
#pragma unroll
    for (int j = 0; j < 16; ++j) {
        int col = 8 * j + 2 * tt;
        *reinterpret_cast<unsigned*>(O + base + (size_t)(q0 + r0) * 128 + col) =
            pack2(o_[j][0] * i0, o_[j][1] * i0);
        *reinterpret_cast<unsigned*>(O + base + (size_t)(q0 + r0 + 8) * 128 + col) =
            pack2(o_[j][2] * i1, o_[j][3] * i1);
    }
}

// ---------------- Kernel 4: O-proj + bias + transpose + residual ----------------
#define OP_SMEM (2 * TILE_BYTES + 128 * 132 * 4)
__global__ __launch_bounds__(256, 1) void oproj_kernel(
    const bf16* __restrict__ o, const bf16* __restrict__ wo, const float* __restrict__ bo,
    const float* __restrict__ x, float* __restrict__ out) {
    extern __shared__ char sm[];
    unsigned sb = cvta_s(sm);
    int tid = threadIdx.x, lane = tid & 31, w = tid >> 5;
    int g = lane >> 2, tt = lane & 3, lm = lane >> 3, lr = lane & 7;
    int b = blockIdx.x >> 3, s0 = (blockIdx.x & 7) * 128;
    size_t m0 = (size_t)blockIdx.x * 128;

    for (int i = tid; i < 2048; i += 256) {
        int row = i >> 4, seg = i & 15;
        CP16(sb + row * 272 + seg * 16, o + (m0 + row) * 128 + seg * 8);
        CP16(sb + TILE_BYTES + row * 272 + seg * 16, wo + row * 128 + seg * 8);
    }
    CP_COMMIT();
    asm volatile("cp.async.wait_group 0;");
    __syncthreads();

    int wm = (w >> 1) * 32, wn = (w & 1) * 64;
    unsigned swb = sb + TILE_BYTES;
    unsigned af[2][8][4];
#pragma unroll
    for (int mi = 0; mi < 2; ++mi)
#pragma unroll
        for (int kk = 0; kk < 8; ++kk) {
            unsigned addr = sb + (unsigned)(wm + 16 * mi + 8 * (lm & 1) + lr) * 272
                          + (unsigned)(kk * 32 + (lm >> 1) * 16);
            ldm_x4(af[mi][kk], addr);
        }

    float acc[2][8][4];
#pragma unroll
    for (int mi = 0; mi < 2; ++mi)
#pragma unroll
        for (int j = 0; j < 8; ++j)
#pragma unroll
            for (int r = 0; r < 4; ++r) acc[mi][j][r] = 0.f;
#pragma unroll
    for (int kk = 0; kk < 8; ++kk)
#pragma unroll
        for (int jp = 0; jp < 4; ++jp) {
            unsigned kb[4];
            unsigned addr = swb + (unsigned)(wn + 16 * jp + 8 * (lm >> 1) + lr) * 272
                          + (unsigned)(kk * 32 + (lm & 1) * 16);
            ldm_x4(kb, addr);
            mma_bf16(acc[0][2 * jp], af[0][kk], kb[0], kb[1]);
            mma_bf16(acc[0][2 * jp + 1], af[0][kk], kb[2], kb[3]);
            mma_bf16(acc[1][2 * jp], af[1][kk], kb[0], kb[1]);
            mma_bf16(acc[1][2 * jp + 1], af[1][kk], kb[2], kb[3]);
        }

    float* tile = reinterpret_cast<float*>(sm + 2 * TILE_BYTES);
#pragma unroll
    for (int mi = 0; mi < 2; ++mi) {
        int r = wm + 16 * mi + g;
#pragma unroll
        for (int j = 0; j < 8; ++j) {
            int col = wn + 8 * j + 2 * tt;
            float b0f = bo[col], b1f = bo[col + 1];
            tile[col * 132 + r] = acc[mi][j][0] + b0f;
            tile[(col + 1) * 132 + r] = acc[mi][j][1] + b1f;
            tile[col * 132 + r + 8] = acc[mi][j][2] + b0f;
            tile[(col + 1) * 132 + r + 8] = acc[mi][j][3] + b1f;
        }
    }
    __syncthreads();
#pragma unroll
    for (int it = 0; it < 16; ++it) {
        int c = (tid >> 5) + 8 * it;
        int s4 = (tid & 31) * 4;
        float4 vv = *reinterpret_cast<float4*>(&tile[c * 132 + s4]);
        size_t gi = ((size_t)b * C_ + c) * S_ + s0 + s4;
        float4 xr = *reinterpret_cast<const float4*>(&x[gi]);
        vv.x += xr.x; vv.y += xr.y; vv.z += xr.z; vv.w += xr.w;
        *reinterpret_cast<float4*>(&out[gi]) = vv;
    }
}

// ---------------- launch ----------------
extern "C" void kernel_launch(void* const* d_in, const int* in_sizes, int n_in,
                              void* d_out, int out_size) {
    const float* x    = (const float*)d_in[0];
    const float* gn_w = (const float*)d_in[1];
    const float* gn_b = (const float*)d_in[2];
    const float* wq   = (const float*)d_in[3];
    const float* bq   = (const float*)d_in[4];
    const float* wk   = (const float*)d_in[5];
    const float* bk   = (const float*)d_in[6];
    const float* wv   = (const float*)d_in[7];
    const float* bv   = (const float*)d_in[8];
    const float* wo   = (const float*)d_in[9];
    const float* bo   = (const float*)d_in[10];
    float* out = (float*)d_out;

    bf16 *t, *v, *o, *wb;
    unsigned char *q8, *k8;
    cudaGetSymbolAddress((void**)&t, g_t);
    cudaGetSymbolAddress((void**)&q8, g_q8);
    cudaGetSymbolAddress((void**)&k8, g_k8);
    cudaGetSymbolAddress((void**)&v, g_v);
    cudaGetSymbolAddress((void**)&o, g_o);
    cudaGetSymbolAddress((void**)&wb, g_wb);

    cudaFuncSetAttribute(qkv_kernel, cudaFuncAttributeMaxDynamicSharedMemorySize, QKV_SMEM);
    cudaFuncSetAttribute(attn_kernel, cudaFuncAttributeMaxDynamicSharedMemorySize, ATT_SMEM);
    cudaFuncSetAttribute(oproj_kernel, cudaFuncAttributeMaxDynamicSharedMemorySize, OP_SMEM);

    convw_kernel<<<64, 256>>>(wq, wk, wv, wo, wb);
    gn_kernel<<<B_ * 32, 256>>>(x, gn_w, gn_b, t);
    qkv_kernel<<<512, 256, QKV_SMEM>>>(t, wb, bq, bk, bv, q8, k8, v);
    attn_kernel<<<1024, 128, ATT_SMEM>>>(q8, k8, v, o);
    oproj_kernel<<<512, 256, OP_SMEM>>>(o, wb + 3 * 16384, bo, x, out);
}

// round 11
// speedup vs baseline: 1.4329x; 1.4329x over previous
#include <cuda_runtime.h>
#include <cuda_bf16.h>
#include <math.h>

#define B_  64
#define C_  128
#define S_  1024
#define EPS 1e-6f
#define SCALE_ 0.044194173824159216f
#define LOG2E_ 1.4426950408889634f

typedef __nv_bfloat16 bf16;

// ---------------- scratch (device globals) ----------------
__device__ bf16 g_t[(size_t)B_ * S_ * C_];
__device__ bf16 g_q[(size_t)B_ * S_ * C_];
__device__ bf16 g_k[(size_t)B_ * S_ * C_];
__device__ bf16 g_v[(size_t)B_ * S_ * C_];
__device__ bf16 g_o[(size_t)B_ * S_ * C_];
__device__ bf16 g_wb[4 * 16384];   // wq, wk, wv, wo in bf16

// ---------------- helpers ----------------
__device__ __forceinline__ unsigned pack2(float a, float b) {
    __nv_bfloat162 h = __floats2bfloat162_rn(a, b);
    return *reinterpret_cast<unsigned*>(&h);
}
__device__ __forceinline__ float ex2(float x) {
    float r; asm("ex2.approx.ftz.f32 %0, %1;" : "=f"(r) : "f"(x)); return r;
}
__device__ __forceinline__ void mma_bf16(float* d, const unsigned* a, unsigned b0, unsigned b1) {
    asm volatile(
        "mma.sync.aligned.m16n8k16.row.col.f32.bf16.bf16.f32 "
        "{%0,%1,%2,%3}, {%4,%5,%6,%7}, {%8,%9}, {%0,%1,%2,%3};\n"
        : "+f"(d[0]), "+f"(d[1]), "+f"(d[2]), "+f"(d[3])
        : "r"(a[0]), "r"(a[1]), "r"(a[2]), "r"(a[3]), "r"(b0), "r"(b1));
}
__device__ __forceinline__ void ldm_x4(unsigned* r, unsigned addr) {
    asm volatile("ldmatrix.sync.aligned.m8n8.x4.shared.b16 {%0,%1,%2,%3}, [%4];"
                 : "=r"(r[0]), "=r"(r[1]), "=r"(r[2]), "=r"(r[3]) : "r"(addr));
}
__device__ __forceinline__ void ldm_x4t(unsigned* r, unsigned addr) {
    asm volatile("ldmatrix.sync.aligned.m8n8.x4.trans.shared.b16 {%0,%1,%2,%3}, [%4];"
                 : "=r"(r[0]), "=r"(r[1]), "=r"(r[2]), "=r"(r[3]) : "r"(addr));
}
__device__ __forceinline__ unsigned cvta_s(const void* p) {
    return (unsigned)__cvta_generic_to_shared(p);
}
#define CP16(dst, src) asm volatile("cp.async.cg.shared.global [%0], [%1], 16;" :: "r"(dst), "l"(src))
#define CP_COMMIT() asm volatile("cp.async.commit_group;")

#define KV_BYTES 17408     // 64 * 272
#define W_BYTES  34816     // 128 * 272

// ---------------- Kernel 0: convert weights fp32 -> bf16 ----------------
__global__ void convw_kernel(const float* __restrict__ wq, const float* __restrict__ wk,
                             const float* __restrict__ wv, const float* __restrict__ wo,
                             bf16* __restrict__ dst) {
    int i = blockIdx.x * 256 + threadIdx.x;
    const float* s;
    int m = i >> 12;
    if (m == 0) s = wq; else if (m == 1) s = wk; else if (m == 2) s = wv; else s = wo;
    float4 v = reinterpret_cast<const float4*>(s)[i & 4095];
    uint2 u; u.x = pack2(v.x, v.y); u.y = pack2(v.z, v.w);
    reinterpret_cast<uint2*>(dst)[i] = u;
}

// ---------------- Kernel 1: GroupNorm -> t[b,s,c] (bf16) ----------------
__global__ void gn_kernel(const float* __restrict__ x, const float* __restrict__ gw,
                          const float* __restrict__ gb, bf16* __restrict__ t) {
    int b = blockIdx.x >> 5, g = blockIdx.x & 31, tid = threadIdx.x;
    const float* xb = x + ((size_t)b * C_ + g * 4) * S_;
    float vals[4][4], s1 = 0.f, s2 = 0.f;
#pragma unroll
    for (int it = 0; it < 4; ++it) {
        int s = tid + it * 256;
#pragma unroll
        for (int j = 0; j < 4; ++j) {
            float v = xb[(size_t)j * S_ + s];
            vals[it][j] = v; s1 += v; s2 += v * v;
        }
    }
    __shared__ float red0[256], red1[256];
    red0[tid] = s1; red1[tid] = s2;
    __syncthreads();
    for (int off = 128; off > 0; off >>= 1) {
        if (tid < off) { red0[tid] += red0[tid + off]; red1[tid] += red1[tid + off]; }
        __syncthreads();
    }
    __shared__ float mean_s, inv_s;
    if (tid == 0) {
        float m = red0[0] * (1.f / 4096.f);
        float var = red1[0] * (1.f / 4096.f) - m * m;
        mean_s = m; inv_s = rsqrtf(var + EPS);
    }
    __syncthreads();
    float m = mean_s, inv = inv_s, w4[4], b4[4];
#pragma unroll
    for (int j = 0; j < 4; ++j) { w4[j] = gw[g * 4 + j]; b4[j] = gb[g * 4 + j]; }
#pragma unroll
    for (int it = 0; it < 4; ++it) {
        int s = tid + it * 256;
        uint2 u;
        u.x = pack2((vals[it][0] - m) * inv * w4[0] + b4[0], (vals[it][1] - m) * inv * w4[1] + b4[1]);
        u.y = pack2((vals[it][2] - m) * inv * w4[2] + b4[2], (vals[it][3] - m) * inv * w4[3] + b4[3]);
        *reinterpret_cast<uint2*>(&t[((size_t)b * S_ + s) * C_ + g * 4]) = u;
    }
}

// ---------------- Kernel 2: 64-row GEMM, 128 threads, 2 CTAs/SM ----------------
// Out[m][n] = (A[m][:] . W[n][:] + bias[n]) * sc ; A 64 rows, W 128x128.
#define G64_SMEM (KV_BYTES + W_BYTES)   // 52224
__global__ __launch_bounds__(128, 2) void gemm64_kernel(
    const bf16* __restrict__ A, const bf16* __restrict__ W,
    const float* __restrict__ bias, bf16* __restrict__ Out, float sc) {
    extern __shared__ char sm[];
    unsigned sb = cvta_s(sm);
    unsigned sw = sb + KV_BYTES;
    int tid = threadIdx.x, lane = tid & 31, w = tid >> 5;
    int g = lane >> 2, tt = lane & 3, lm = lane >> 3, lr = lane & 7;
    size_t m0 = (size_t)blockIdx.x * 64;

    for (int i = tid; i < 1024; i += 128) {
        int row = i >> 4, seg = i & 15;
        CP16(sb + row * 272 + seg * 16, A + (m0 + row) * 128 + seg * 8);
    }
    for (int i = tid; i < 2048; i += 128) {
        int row = i >> 4, seg = i & 15;
        CP16(sw + row * 272 + seg * 16, W + (size_t)row * 128 + seg * 8);
    }
    CP_COMMIT();
    asm volatile("cp.async.wait_group 0;");
    __syncthreads();

    // A fragments: warp w owns rows [16w, 16w+16)
    unsigned af[8][4];
#pragma unroll
    for (int kk = 0; kk < 8; ++kk) {
        unsigned addr = sb + (unsigned)(w * 16 + 8 * (lm & 1) + lr) * 272
                      + (unsigned)(kk * 32 + (lm >> 1) * 16);
        ldm_x4(af[kk], addr);
    }

    float acc[16][4];
#pragma unroll
    for (int j = 0; j < 16; ++j)
#pragma unroll
        for (int r = 0; r < 4; ++r) acc[j][r] = 0.f;

#pragma unroll
    for (int kk = 0; kk < 8; ++kk)
#pragma unroll
        for (int jp = 0; jp < 8; ++jp) {
            unsigned kb[4];
            unsigned addr = sw + (unsigned)(16 * jp + 8 * (lm >> 1) + lr) * 272
                          + (unsigned)(kk * 32 + (lm & 1) * 16);
            ldm_x4(kb, addr);
            mma_bf16(acc[2 * jp], af[kk], kb[0], kb[1]);
            mma_bf16(acc[2 * jp + 1], af[kk], kb[2], kb[3]);
        }

    int r0 = w * 16 + g;
#pragma unroll
    for (int j = 0; j < 16; ++j) {
        int col = 8 * j + 2 * tt;
        float b0f = bias[col], b1f = bias[col + 1];
        *reinterpret_cast<unsigned*>(Out + (m0 + r0) * 128 + col) =
            pack2((acc[j][0] + b0f) * sc, (acc[j][1] + b1f) * sc);
        *reinterpret_cast<unsigned*>(Out + (m0 + r0 + 8) * 128 + col) =
            pack2((acc[j][2] + b0f) * sc, (acc[j][3] + b1f) * sc);
    }
}

// ---------------- Kernel 3: flash attention (R6, bf16, 64 rows, 2 CTAs/SM) ----------------
#define ATT_Q_BYTES 17408
#define ATT_SMEM (ATT_Q_BYTES + 4 * KV_BYTES)   // 87040
__global__ __launch_bounds__(128, 2) void attn_kernel(
    const bf16* __restrict__ Q, const bf16* __restrict__ K,
    const bf16* __restrict__ V, bf16* __restrict__ O) {
    extern __shared__ char sm[];
    unsigned sb = cvta_s(sm);
    int tid = threadIdx.x, lane = tid & 31, w = tid >> 5;
    int g = lane >> 2, tt = lane & 3;
    int lm = lane >> 3, lr = lane & 7;
    int b = blockIdx.x >> 4, qt = blockIdx.x & 15;
    size_t base = (size_t)b * S_ * C_;
    int q0 = qt * 64;
    int r0 = w * 16 + g;

    for (int i = tid; i < 1024; i += 128) {
        int row = i >> 4, seg = i & 15;
        CP16(sb + row * 272 + seg * 16, Q + base + (size_t)(q0 + row) * 128 + seg * 8);
        CP16(sb + ATT_Q_BYTES + row * 272 + seg * 16, K + base + (size_t)row * 128 + seg * 8);
        CP16(sb + ATT_Q_BYTES + KV_BYTES + row * 272 + seg * 16, V + base + (size_t)row * 128 + seg * 8);
    }
    CP_COMMIT();
    asm volatile("cp.async.wait_group 0;");
    __syncthreads();

    unsigned qa[8][4];
#pragma unroll
    for (int kk = 0; kk < 8; ++kk) {
        unsigned addr = sb + (unsigned)(w * 16 + 8 * (lm & 1) + lr) * 272
                      + (unsigned)(kk * 32 + (lm >> 1) * 16);
        ldm_x4(qa[kk], addr);
    }

    float o_[16][4];
#pragma unroll
    for (int j = 0; j < 16; ++j)
#pragma unroll
        for (int r = 0; r < 4; ++r) o_[j][r] = 0.f;
    float l0 = 0.f, l1 = 0.f;

    CP_COMMIT();

    for (int kt = 0; kt < 16; ++kt) {
        int cur = kt & 1;
        asm volatile("cp.async.wait_group 0;");
        __syncthreads();

        if (kt < 15) {
            unsigned kdst = sb + ATT_Q_BYTES + (1 - cur) * (2 * KV_BYTES);
            const bf16* ksrc = K + base + (size_t)(kt + 1) * 64 * 128;
            const bf16* vsrc = V + base + (size_t)(kt + 1) * 64 * 128;
            for (int i = tid; i < 1024; i += 128) {
                int row = i >> 4, seg = i & 15;
                CP16(kdst + row * 272 + seg * 16, ksrc + (size_t)row * 128 + seg * 8);
                CP16(kdst + KV_BYTES + row * 272 + seg * 16, vsrc + (size_t)row * 128 + seg * 8);
            }
        }
        CP_COMMIT();

        unsigned skb = sb + ATT_Q_BYTES + cur * (2 * KV_BYTES);
        unsigned svb = skb + KV_BYTES;

        float s[8][4];
#pragma unroll
        for (int j = 0; j < 8; ++j)
#pragma unroll
            for (int r = 0; r < 4; ++r) s[j][r] = 0.f;
#pragma unroll
        for (int kk = 0; kk < 8; ++kk)
#pragma unroll
            for (int jp = 0; jp < 4; ++jp) {
                unsigned kb[4];
                unsigned addr = skb + (unsigned)(16 * jp + 8 * (lm >> 1) + lr) * 272
                              + (unsigned)(kk * 32 + (lm & 1) * 16);
                ldm_x4(kb, addr);
                mma_bf16(s[2 * jp], qa[kk], kb[0], kb[1]);
                mma_bf16(s[2 * jp + 1], qa[kk], kb[2], kb[3]);
            }

        unsigned pa[4][4];
#pragma unroll
        for (int j = 0; j < 8; ++j) {
            float p00 = ex2(s[j][0]), p01 = ex2(s[j][1]);
            float p10 = ex2(s[j][2]), p11 = ex2(s[j][3]);
            l0 += p00 + p01; l1 += p10 + p11;
            pa[j >> 1][(j & 1) * 2 + 0] = pack2(p00, p01);
            pa[j >> 1][(j & 1) * 2 + 1] = pack2(p10, p11);
        }

#pragma unroll
        for (int kt2 = 0; kt2 < 4; ++kt2) {
#pragma unroll
            for (int jp = 0; jp < 8; ++jp) {
                unsigned vb[4];
                unsigned addr = svb + (unsigned)(kt2 * 16 + 8 * (lm & 1) + lr) * 272
                              + (unsigned)((2 * jp + (lm >> 1)) * 16);
                ldm_x4t(vb, addr);
                mma_bf16(o_[2 * jp], pa[kt2], vb[0], vb[1]);
                mma_bf16(o_[2 * jp + 1], pa[kt2], vb[2], vb[3]);
            }
        }
    }

    l0 += __shfl_xor_sync(0xffffffffu, l0, 1);
    l0 += __shfl_xor_sync(0xffffffffu, l0, 2);
    l1 += __shfl_xor_sync(0xffffffffu, l1, 1);
    l1 += __shfl_xor_sync(0xffffffffu, l1, 2);
    float i0 = 1.f / l0, i1 = 1.f / l1;
#pragma unroll
    for (int j = 0; j < 16; ++j) {
        int col = 8 * j + 2 * tt;
        *reinterpret_cast<unsigned*>(O + base + (size_t)(q0 + r0) * 128 + col) =
            pack2(o_[j][0] * i0, o_[j][1] * i0);
        *reinterpret_cast<unsigned*>(O + base + (size_t)(q0 + r0 + 8) * 128 + col) =
            pack2(o_[j][2] * i1, o_[j][3] * i1);
    }
}

// ---------------- Kernel 4: 64-row O-proj + bias + transpose + residual, 2 CTAs/SM ----------------
#define OP64_SMEM (KV_BYTES + W_BYTES)   // 52224 ; transpose tile reuses W region (34816 = 128*68*4)
__global__ __launch_bounds__(128, 2) void oproj64_kernel(
    const bf16* __restrict__ o, const bf16* __restrict__ wo, const float* __restrict__ bo,
    const float* __restrict__ x, float* __restrict__ out) {
    extern __shared__ char sm[];
    unsigned sb = cvta_s(sm);
    unsigned sw = sb + KV_BYTES;
    int tid = threadIdx.x, lane = tid & 31, w = tid >> 5;
    int g = lane >> 2, tt = lane & 3, lm = lane >> 3, lr = lane & 7;
    int b = blockIdx.x >> 4, s0 = (blockIdx.x & 15) * 64;
    size_t m0 = (size_t)blockIdx.x * 64;

    for (int i = tid; i < 1024; i += 128) {
        int row = i >> 4, seg = i & 15;
        CP16(sb + row * 272 + seg * 16, o + (m0 + row) * 128 + seg * 8);
    }
    for (int i = tid; i < 2048; i += 128) {
        int row = i >> 4, seg = i & 15;
        CP16(sw + row * 272 + seg * 16, wo + (size_t)row * 128 + seg * 8);
    }
    CP_COMMIT();
    asm volatile("cp.async.wait_group 0;");
    __syncthreads();

    unsigned af[8][4];
#pragma unroll
    for (int kk = 0; kk < 8; ++kk) {
        unsigned addr = sb + (unsigned)(w * 16 + 8 * (lm & 1) + lr) * 272
                      + (unsigned)(kk * 32 + (lm >> 1) * 16);
        ldm_x4(af[kk], addr);
    }

    float acc[16][4];
#pragma unroll
    for (int j = 0; j < 16; ++j)
#pragma unroll
        for (int r = 0; r < 4; ++r) acc[j][r] = 0.f;

#pragma unroll
    for (int kk = 0; kk < 8; ++kk)
#pragma unroll
        for (int jp = 0; jp < 8; ++jp) {
            unsigned kb[4];
            unsigned addr = sw + (unsigned)(16 * jp + 8 * (lm >> 1) + lr) * 272
                          + (unsigned)(kk * 32 + (lm & 1) * 16);
            ldm_x4(kb, addr);
            mma_bf16(acc[2 * jp], af[kk], kb[0], kb[1]);
            mma_bf16(acc[2 * jp + 1], af[kk], kb[2], kb[3]);
        }
    __syncthreads();   // all warps done reading W; reuse region as transpose tile

    // transposed store: tile[col][row], pitch 68 floats
    float* tile = reinterpret_cast<float*>(sm + KV_BYTES);
    int r0 = w * 16 + g;
#pragma unroll
    for (int j = 0; j < 16; ++j) {
        int col = 8 * j + 2 * tt;
        float b0f = bo[col], b1f = bo[col + 1];
        tile[col * 68 + r0] = acc[j][0] + b0f;
        tile[(col + 1) * 68 + r0] = acc[j][1] + b1f;
        tile[col * 68 + r0 + 8] = acc[j][2] + b0f;
        tile[(col + 1) * 68 + r0 + 8] = acc[j][3] + b1f;
    }
    __syncthreads();

#pragma unroll
    for (int it = 0; it < 16; ++it) {
        int c = (tid >> 4) + 8 * it;
        int s4 = (tid & 15) * 4;
        float4 vv = *reinterpret_cast<float4*>(&tile[c * 68 + s4]);
        size_t gi = ((size_t)b * C_ + c) * S_ + s0 + s4;
        float4 xr = *reinterpret_cast<const float4*>(&x[gi]);
        vv.x += xr.x; vv.y += xr.y; vv.z += xr.z; vv.w += xr.w;
        *reinterpret_cast<float4*>(&out[gi]) = vv;
    }
}

// ---------------- launch ----------------
extern "C" void kernel_launch(void* const* d_in, const int* in_sizes, int n_in,
                              void* d_out, int out_size) {
    const float* x    = (const float*)d_in[0];
    const float* gn_w = (const float*)d_in[1];
    const float* gn_b = (const float*)d_in[2];
    const float* wq   = (const float*)d_in[3];
    const float* bq   = (const float*)d_in[4];
    const float* wk   = (const float*)d_in[5];
    const float* bk   = (const float*)d_in[6];
    const float* wv   = (const float*)d_in[7];
    const float* bv   = (const float*)d_in[8];
    const float* wo   = (const float*)d_in[9];
    const float* bo   = (const float*)d_in[10];
    float* out = (float*)d_out;

    bf16 *t, *q, *k, *v, *o, *wb;
    cudaGetSymbolAddress((void**)&t, g_t);
    cudaGetSymbolAddress((void**)&q, g_q);
    cudaGetSymbolAddress((void**)&k, g_k);
    cudaGetSymbolAddress((void**)&v, g_v);
    cudaGetSymbolAddress((void**)&o, g_o);
    cudaGetSymbolAddress((void**)&wb, g_wb);

    cudaFuncSetAttribute(gemm64_kernel, cudaFuncAttributeMaxDynamicSharedMemorySize, G64_SMEM);
    cudaFuncSetAttribute(attn_kernel, cudaFuncAttributeMaxDynamicSharedMemorySize, ATT_SMEM);
    cudaFuncSetAttribute(oproj64_kernel, cudaFuncAttributeMaxDynamicSharedMemorySize, OP64_SMEM);

    convw_kernel<<<64, 256>>>(wq, wk, wv, wo, wb);
    gn_kernel<<<B_ * 32, 256>>>(x, gn_w, gn_b, t);

    int mblocks = (B_ * S_) / 64;   // 1024
    gemm64_kernel<<<mblocks, 128, G64_SMEM>>>(t, wb,             bq, q, SCALE_ * LOG2E_);
    gemm64_kernel<<<mblocks, 128, G64_SMEM>>>(t, wb + 16384,     bk, k, 1.f);
    gemm64_kernel<<<mblocks, 128, G64_SMEM>>>(t, wb + 2 * 16384, bv, v, 1.f);

    attn_kernel<<<1024, 128, ATT_SMEM>>>(q, k, v, o);

    oproj64_kernel<<<mblocks, 128, OP64_SMEM>>>(o, wb + 3 * 16384, bo, x, out);
}

// round 14
// speedup vs baseline: 1.4943x; 1.0428x over previous
#include <cuda_runtime.h>
#include <cuda_bf16.h>
#include <math.h>

#define B_  64
#define C_  128
#define S_  1024
#define EPS 1e-6f
#define SCALE_ 0.044194173824159216f
#define LOG2E_ 1.4426950408889634f

typedef __nv_bfloat16 bf16;

// ---------------- scratch (device globals) ----------------
__device__ bf16 g_t[(size_t)B_ * S_ * C_];
__device__ bf16 g_q[(size_t)B_ * S_ * C_];
__device__ bf16 g_k[(size_t)B_ * S_ * C_];
__device__ bf16 g_v[(size_t)B_ * S_ * C_];
__device__ bf16 g_o[(size_t)B_ * S_ * C_];
__device__ bf16 g_wb[4 * 16384];   // wq, wk, wv, wo in bf16

// ---------------- helpers ----------------
__device__ __forceinline__ unsigned pack2(float a, float b) {
    __nv_bfloat162 h = __floats2bfloat162_rn(a, b);
    return *reinterpret_cast<unsigned*>(&h);
}
__device__ __forceinline__ float ex2(float x) {
    float r; asm("ex2.approx.ftz.f32 %0, %1;" : "=f"(r) : "f"(x)); return r;
}
__device__ __forceinline__ void mma_bf16(float* d, const unsigned* a, unsigned b0, unsigned b1) {
    asm volatile(
        "mma.sync.aligned.m16n8k16.row.col.f32.bf16.bf16.f32 "
        "{%0,%1,%2,%3}, {%4,%5,%6,%7}, {%8,%9}, {%0,%1,%2,%3};\n"
        : "+f"(d[0]), "+f"(d[1]), "+f"(d[2]), "+f"(d[3])
        : "r"(a[0]), "r"(a[1]), "r"(a[2]), "r"(a[3]), "r"(b0), "r"(b1));
}
__device__ __forceinline__ void ldm_x4(unsigned* r, unsigned addr) {
    asm volatile("ldmatrix.sync.aligned.m8n8.x4.shared.b16 {%0,%1,%2,%3}, [%4];"
                 : "=r"(r[0]), "=r"(r[1]), "=r"(r[2]), "=r"(r[3]) : "r"(addr));
}
__device__ __forceinline__ void ldm_x4t(unsigned* r, unsigned addr) {
    asm volatile("ldmatrix.sync.aligned.m8n8.x4.trans.shared.b16 {%0,%1,%2,%3}, [%4];"
                 : "=r"(r[0]), "=r"(r[1]), "=r"(r[2]), "=r"(r[3]) : "r"(addr));
}
__device__ __forceinline__ unsigned cvta_s(const void* p) {
    return (unsigned)__cvta_generic_to_shared(p);
}
#define CP16(dst, src) asm volatile("cp.async.cg.shared.global [%0], [%1], 16;" :: "r"(dst), "l"(src))
#define CP_COMMIT() asm volatile("cp.async.commit_group;")

#define KV_BYTES 17408     // 64 * 272
#define W_BYTES  34816     // 128 * 272

// ---------------- Kernel 0: convert weights fp32 -> bf16 ----------------
__global__ void convw_kernel(const float* __restrict__ wq, const float* __restrict__ wk,
                             const float* __restrict__ wv, const float* __restrict__ wo,
                             bf16* __restrict__ dst) {
    int i = blockIdx.x * 256 + threadIdx.x;
    const float* s;
    int m = i >> 12;
    if (m == 0) s = wq; else if (m == 1) s = wk; else if (m == 2) s = wv; else s = wo;
    float4 v = reinterpret_cast<const float4*>(s)[i & 4095];
    uint2 u; u.x = pack2(v.x, v.y); u.y = pack2(v.z, v.w);
    reinterpret_cast<uint2*>(dst)[i] = u;
}

// ---------------- Kernel 1: GroupNorm -> t[b,s,c] (bf16) ----------------
__global__ void gn_kernel(const float* __restrict__ x, const float* __restrict__ gw,
                          const float* __restrict__ gb, bf16* __restrict__ t) {
    int b = blockIdx.x >> 5, g = blockIdx.x & 31, tid = threadIdx.x;
    const float* xb = x + ((size_t)b * C_ + g * 4) * S_;
    float vals[4][4], s1 = 0.f, s2 = 0.f;
#pragma unroll
    for (int it = 0; it < 4; ++it) {
        int s = tid + it * 256;
#pragma unroll
        for (int j = 0; j < 4; ++j) {
            float v = xb[(size_t)j * S_ + s];
            vals[it][j] = v; s1 += v; s2 += v * v;
        }
    }
    __shared__ float red0[256], red1[256];
    red0[tid] = s1; red1[tid] = s2;
    __syncthreads();
    for (int off = 128; off > 0; off >>= 1) {
        if (tid < off) { red0[tid] += red0[tid + off]; red1[tid] += red1[tid + off]; }
        __syncthreads();
    }
    __shared__ float mean_s, inv_s;
    if (tid == 0) {
        float m = red0[0] * (1.f / 4096.f);
        float var = red1[0] * (1.f / 4096.f) - m * m;
        mean_s = m; inv_s = rsqrtf(var + EPS);
    }
    __syncthreads();
    float m = mean_s, inv = inv_s, w4[4], b4[4];
#pragma unroll
    for (int j = 0; j < 4; ++j) { w4[j] = gw[g * 4 + j]; b4[j] = gb[g * 4 + j]; }
#pragma unroll
    for (int it = 0; it < 4; ++it) {
        int s = tid + it * 256;
        uint2 u;
        u.x = pack2((vals[it][0] - m) * inv * w4[0] + b4[0], (vals[it][1] - m) * inv * w4[1] + b4[1]);
        u.y = pack2((vals[it][2] - m) * inv * w4[2] + b4[2], (vals[it][3] - m) * inv * w4[3] + b4[3]);
        *reinterpret_cast<uint2*>(&t[((size_t)b * S_ + s) * C_ + g * 4]) = u;
    }
}

// ---------------- Kernel 2: GEMM x4 — resident W, 4 x 64-row A tiles, 2 CTAs/SM ----------------
#define GX_SMEM (2 * KV_BYTES + W_BYTES)   // 69632
__global__ __launch_bounds__(128, 2) void gemmx4_kernel(
    const bf16* __restrict__ A, const bf16* __restrict__ W,
    const float* __restrict__ bias, bf16* __restrict__ Out, float sc) {
    extern __shared__ char sm[];
    unsigned sb = cvta_s(sm);
    unsigned sw = sb + 2 * KV_BYTES;
    int tid = threadIdx.x, lane = tid & 31, w = tid >> 5;
    int g = lane >> 2, tt = lane & 3, lm = lane >> 3, lr = lane & 7;
    size_t m0 = (size_t)blockIdx.x * 256;

    // prologue: W + A tile 0
    for (int i = tid; i < 2048; i += 128) {
        int row = i >> 4, seg = i & 15;
        CP16(sw + row * 272 + seg * 16, W + (size_t)row * 128 + seg * 8);
    }
    for (int i = tid; i < 1024; i += 128) {
        int row = i >> 4, seg = i & 15;
        CP16(sb + row * 272 + seg * 16, A + (m0 + row) * 128 + seg * 8);
    }
    CP_COMMIT();
    asm volatile("cp.async.wait_group 0;");
    __syncthreads();

    int r0 = w * 16 + g;
#pragma unroll 1
    for (int t = 0; t < 4; ++t) {
        unsigned sa = sb + (unsigned)(t & 1) * KV_BYTES;
        // prefetch next A tile into the other buffer
        if (t < 3) {
            unsigned sa_alt = sb + (unsigned)(1 - (t & 1)) * KV_BYTES;
            const bf16* an = A + (m0 + (size_t)(t + 1) * 64) * 128;
            for (int i = tid; i < 1024; i += 128) {
                int row = i >> 4, seg = i & 15;
                CP16(sa_alt + row * 272 + seg * 16, an + (size_t)row * 128 + seg * 8);
            }
            CP_COMMIT();
        }

        unsigned af[8][4];
#pragma unroll
        for (int kk = 0; kk < 8; ++kk) {
            unsigned addr = sa + (unsigned)(w * 16 + 8 * (lm & 1) + lr) * 272
                          + (unsigned)(kk * 32 + (lm >> 1) * 16);
            ldm_x4(af[kk], addr);
        }

        float acc[16][4];
#pragma unroll
        for (int j = 0; j < 16; ++j)
#pragma unroll
            for (int r = 0; r < 4; ++r) acc[j][r] = 0.f;

#pragma unroll
        for (int kk = 0; kk < 8; ++kk)
#pragma unroll
            for (int jp = 0; jp < 8; ++jp) {
                unsigned kb[4];
                unsigned addr = sw + (unsigned)(16 * jp + 8 * (lm >> 1) + lr) * 272
                              + (unsigned)(kk * 32 + (lm & 1) * 16);
                ldm_x4(kb, addr);
                mma_bf16(acc[2 * jp], af[kk], kb[0], kb[1]);
                mma_bf16(acc[2 * jp + 1], af[kk], kb[2], kb[3]);
            }

        size_t mrow = m0 + (size_t)t * 64 + r0;
#pragma unroll
        for (int j = 0; j < 16; ++j) {
            int col = 8 * j + 2 * tt;
            float b0f = bias[col], b1f = bias[col + 1];
            *reinterpret_cast<unsigned*>(Out + mrow * 128 + col) =
                pack2((acc[j][0] + b0f) * sc, (acc[j][1] + b1f) * sc);
            *reinterpret_cast<unsigned*>(Out + (mrow + 8) * 128 + col) =
                pack2((acc[j][2] + b0f) * sc, (acc[j][3] + b1f) * sc);
        }

        if (t < 3) {
            asm volatile("cp.async.wait_group 0;");
            __syncthreads();
        }
    }
}

// ---------------- Kernel 3: flash attention (R6 bf16, 64 rows, 2 CTAs/SM) ----------------
#define ATT_Q_BYTES 17408
#define ATT_SMEM (ATT_Q_BYTES + 4 * KV_BYTES)   // 87040
__global__ __launch_bounds__(128, 2) void attn_kernel(
    const bf16* __restrict__ Q, const bf16* __restrict__ K,
    const bf16* __restrict__ V, bf16* __restrict__ O) {
    extern __shared__ char sm[];
    unsigned sb = cvta_s(sm);
    int tid = threadIdx.x, lane = tid & 31, w = tid >> 5;
    int g = lane >> 2, tt = lane & 3;
    int lm = lane >> 3, lr = lane & 7;
    int b = blockIdx.x >> 4, qt = blockIdx.x & 15;
    size_t base = (size_t)b * S_ * C_;
    int q0 = qt * 64;
    int r0 = w * 16 + g;

    for (int i = tid; i < 1024; i += 128) {
        int row = i >> 4, seg = i & 15;
        CP16(sb + row * 272 + seg * 16, Q + base + (size_t)(q0 + row) * 128 + seg * 8);
        CP16(sb + ATT_Q_BYTES + row * 272 + seg * 16, K + base + (size_t)row * 128 + seg * 8);
        CP16(sb + ATT_Q_BYTES + KV_BYTES + row * 272 + seg * 16, V + base + (size_t)row * 128 + seg * 8);
    }
    CP_COMMIT();
    asm volatile("cp.async.wait_group 0;");
    __syncthreads();

    unsigned qa[8][4];
#pragma unroll
    for (int kk = 0; kk < 8; ++kk) {
        unsigned addr = sb + (unsigned)(w * 16 + 8 * (lm & 1) + lr) * 272
                      + (unsigned)(kk * 32 + (lm >> 1) * 16);
        ldm_x4(qa[kk], addr);
    }

    float o_[16][4];
#pragma unroll
    for (int j = 0; j < 16; ++j)
#pragma unroll
        for (int r = 0; r < 4; ++r) o_[j][r] = 0.f;
    float l0 = 0.f, l1 = 0.f;

    CP_COMMIT();

    for (int kt = 0; kt < 16; ++kt) {
        int cur = kt & 1;
        asm volatile("cp.async.wait_group 0;");
        __syncthreads();

        if (kt < 15) {
            unsigned kdst = sb + ATT_Q_BYTES + (1 - cur) * (2 * KV_BYTES);
            const bf16* ksrc = K + base + (size_t)(kt + 1) * 64 * 128;
            const bf16* vsrc = V + base + (size_t)(kt + 1) * 64 * 128;
            for (int i = tid; i < 1024; i += 128) {
                int row = i >> 4, seg = i & 15;
                CP16(kdst + row * 272 + seg * 16, ksrc + (size_t)row * 128 + seg * 8);
                CP16(kdst + KV_BYTES + row * 272 + seg * 16, vsrc + (size_t)row * 128 + seg * 8);
            }
        }
        CP_COMMIT();

        unsigned skb = sb + ATT_Q_BYTES + cur * (2 * KV_BYTES);
        unsigned svb = skb + KV_BYTES;

        float s[8][4];
#pragma unroll
        for (int j = 0; j < 8; ++j)
#pragma unroll
            for (int r = 0; r < 4; ++r) s[j][r] = 0.f;
#pragma unroll
        for (int kk = 0; kk < 8; ++kk)
#pragma unroll
            for (int jp = 0; jp < 4; ++jp) {
                unsigned kb[4];
                unsigned addr = skb + (unsigned)(16 * jp + 8 * (lm >> 1) + lr) * 272
                              + (unsigned)(kk * 32 + (lm & 1) * 16);
                ldm_x4(kb, addr);
                mma_bf16(s[2 * jp], qa[kk], kb[0], kb[1]);
                mma_bf16(s[2 * jp + 1], qa[kk], kb[2], kb[3]);
            }

        unsigned pa[4][4];
#pragma unroll
        for (int j = 0; j < 8; ++j) {
            float p00 = ex2(s[j][0]), p01 = ex2(s[j][1]);
            float p10 = ex2(s[j][2]), p11 = ex2(s[j][3]);
            l0 += p00 + p01; l1 += p10 + p11;
            pa[j >> 1][(j & 1) * 2 + 0] = pack2(p00, p01);
            pa[j >> 1][(j & 1) * 2 + 1] = pack2(p10, p11);
        }

#pragma unroll
        for (int kt2 = 0; kt2 < 4; ++kt2) {
#pragma unroll
            for (int jp = 0; jp < 8; ++jp) {
                unsigned vb[4];
                unsigned addr = svb + (unsigned)(kt2 * 16 + 8 * (lm & 1) + lr) * 272
                              + (unsigned)((2 * jp + (lm >> 1)) * 16);
                ldm_x4t(vb, addr);
                mma_bf16(o_[2 * jp], pa[kt2], vb[0], vb[1]);
                mma_bf16(o_[2 * jp + 1], pa[kt2], vb[2], vb[3]);
            }
        }
    }

    l0 += __shfl_xor_sync(0xffffffffu, l0, 1);
    l0 += __shfl_xor_sync(0xffffffffu, l0, 2);
    l1 += __shfl_xor_sync(0xffffffffu, l1, 1);
    l1 += __shfl_xor_sync(0xffffffffu, l1, 2);
    float i0 = 1.f / l0, i1 = 1.f / l1;
#pragma unroll
    for (int j = 0; j < 16; ++j) {
        int col = 8 * j + 2 * tt;
        *reinterpret_cast<unsigned*>(O + base + (size_t)(q0 + r0) * 128 + col) =
            pack2(o_[j][0] * i0, o_[j][1] * i0);
        *reinterpret_cast<unsigned*>(O + base + (size_t)(q0 + r0 + 8) * 128 + col) =
            pack2(o_[j][2] * i1, o_[j][3] * i1);
    }
}

// ---------------- Kernel 4: O-proj x4 — resident W, transpose + residual, 2 CTAs/SM ----------------
#define OPX_TILE_OFF (2 * KV_BYTES + W_BYTES)            // 69632
#define OPX_SMEM (OPX_TILE_OFF + 128 * 68 * 4)           // 104448 (tile: 128 cols x 68-float pitch)
__global__ __launch_bounds__(128, 2) void oprojx4_kernel(
    const bf16* __restrict__ o, const bf16* __restrict__ wo, const float* __restrict__ bo,
    const float* __restrict__ x, float* __restrict__ out) {
    extern __shared__ char sm[];
    unsigned sb = cvta_s(sm);
    unsigned sw = sb + 2 * KV_BYTES;
    float* tile = reinterpret_cast<float*>(sm + OPX_TILE_OFF);   // [128 cols][68-float pitch], rows 0..63
    int tid = threadIdx.x, lane = tid & 31, w = tid >> 5;
    int g = lane >> 2, tt = lane & 3, lm = lane >> 3, lr = lane & 7;
    size_t m0 = (size_t)blockIdx.x * 256;
    int b = blockIdx.x >> 2;
    int sbase = (blockIdx.x & 3) * 256;

    for (int i = tid; i < 2048; i += 128) {
        int row = i >> 4, seg = i & 15;
        CP16(sw + row * 272 + seg * 16, wo + (size_t)row * 128 + seg * 8);
    }
    for (int i = tid; i < 1024; i += 128) {
        int row = i >> 4, seg = i & 15;
        CP16(sb + row * 272 + seg * 16, o + (m0 + row) * 128 + seg * 8);
    }
    CP_COMMIT();
    asm volatile("cp.async.wait_group 0;");
    __syncthreads();

    int r0 = w * 16 + g;
#pragma unroll 1
    for (int t = 0; t < 4; ++t) {
        unsigned sa = sb + (unsigned)(t & 1) * KV_BYTES;
        if (t < 3) {
            unsigned sa_alt = sb + (unsigned)(1 - (t & 1)) * KV_BYTES;
            const bf16* an = o + (m0 + (size_t)(t + 1) * 64) * 128;
            for (int i = tid; i < 1024; i += 128) {
                int row = i >> 4, seg = i & 15;
                CP16(sa_alt + row * 272 + seg * 16, an + (size_t)row * 128 + seg * 8);
            }
            CP_COMMIT();
        }

        unsigned af[8][4];
#pragma unroll
        for (int kk = 0; kk < 8; ++kk) {
            unsigned addr = sa + (unsigned)(w * 16 + 8 * (lm & 1) + lr) * 272
                          + (unsigned)(kk * 32 + (lm >> 1) * 16);
            ldm_x4(af[kk], addr);
        }

        float acc[16][4];
#pragma unroll
        for (int j = 0; j < 16; ++j)
#pragma unroll
            for (int r = 0; r < 4; ++r) acc[j][r] = 0.f;

#pragma unroll
        for (int kk = 0; kk < 8; ++kk)
#pragma unroll
            for (int jp = 0; jp < 8; ++jp) {
                unsigned kb[4];
                unsigned addr = sw + (unsigned)(16 * jp + 8 * (lm >> 1) + lr) * 272
                              + (unsigned)(kk * 32 + (lm & 1) * 16);
                ldm_x4(kb, addr);
                mma_bf16(acc[2 * jp], af[kk], kb[0], kb[1]);
                mma_bf16(acc[2 * jp + 1], af[kk], kb[2], kb[3]);
            }

        // transpose via smem tile: tile[col][row_in_tile], pitch 68 floats (rows 0..63)
#pragma unroll
        for (int j = 0; j < 16; ++j) {
            int col = 8 * j + 2 * tt;
            float b0f = bo[col], b1f = bo[col + 1];
            tile[col * 68 + r0] = acc[j][0] + b0f;
            tile[(col + 1) * 68 + r0] = acc[j][1] + b1f;
            tile[col * 68 + r0 + 8] = acc[j][2] + b0f;
            tile[(col + 1) * 68 + r0 + 8] = acc[j][3] + b1f;
        }
        __syncthreads();

        int s0 = sbase + t * 64;
#pragma unroll
        for (int it = 0; it < 16; ++it) {
            int c = (tid >> 4) + 8 * it;
            int s4 = (tid & 15) * 4;
            float4 vv = *reinterpret_cast<float4*>(&tile[c * 68 + s4]);
            size_t gi = ((size_t)b * C_ + c) * S_ + s0 + s4;
            float4 xr = *reinterpret_cast<const float4*>(&x[gi]);
            vv.x += xr.x; vv.y += xr.y; vv.z += xr.z; vv.w += xr.w;
            *reinterpret_cast<float4*>(&out[gi]) = vv;
        }

        if (t < 3) {
            asm volatile("cp.async.wait_group 0;");
            __syncthreads();
        }
    }
}

// ---------------- launch ----------------
extern "C" void kernel_launch(void* const* d_in, const int* in_sizes, int n_in,
                              void* d_out, int out_size) {
    const float* x    = (const float*)d_in[0];
    const float* gn_w = (const float*)d_in[1];
    const float* gn_b = (const float*)d_in[2];
    const float* wq   = (const float*)d_in[3];
    const float* bq   = (const float*)d_in[4];
    const float* wk   = (const float*)d_in[5];
    const float* bk   = (const float*)d_in[6];
    const float* wv   = (const float*)d_in[7];
    const float* bv   = (const float*)d_in[8];
    const float* wo   = (const float*)d_in[9];
    const float* bo   = (const float*)d_in[10];
    float* out = (float*)d_out;

    bf16 *t, *q, *k, *v, *o, *wb;
    cudaGetSymbolAddress((void**)&t, g_t);
    cudaGetSymbolAddress((void**)&q, g_q);
    cudaGetSymbolAddress((void**)&k, g_k);
    cudaGetSymbolAddress((void**)&v, g_v);
    cudaGetSymbolAddress((void**)&o, g_o);
    cudaGetSymbolAddress((void**)&wb, g_wb);

    cudaFuncSetAttribute(gemmx4_kernel, cudaFuncAttributeMaxDynamicSharedMemorySize, GX_SMEM);
    cudaFuncSetAttribute(attn_kernel, cudaFuncAttributeMaxDynamicSharedMemorySize, ATT_SMEM);
    cudaFuncSetAttribute(oprojx4_kernel, cudaFuncAttributeMaxDynamicSharedMemorySize, OPX_SMEM);

    convw_kernel<<<64, 256>>>(wq, wk, wv, wo, wb);
    gn_kernel<<<B_ * 32, 256>>>(x, gn_w, gn_b, t);

    int xblocks = (B_ * S_) / 256;   // 256
    gemmx4_kernel<<<xblocks, 128, GX_SMEM>>>(t, wb,             bq, q, SCALE_ * LOG2E_);
    gemmx4_kernel<<<xblocks, 128, GX_SMEM>>>(t, wb + 16384,     bk, k, 1.f);
    gemmx4_kernel<<<xblocks, 128, GX_SMEM>>>(t, wb + 2 * 16384, bv, v, 1.f);

    attn_kernel<<<1024, 128, ATT_SMEM>>>(q, k, v, o);

    oprojx4_kernel<<<xblocks, 128, OPX_SMEM>>>(o, wb + 3 * 16384, bo, x, out);
}

// round 15
// speedup vs baseline: 1.5291x; 1.0233x over previous
#include <cuda_runtime.h>
#include <cuda_bf16.h>
#include <math.h>

#define B_  64
#define C_  128
#define S_  1024
#define EPS 1e-6f
#define SCALE_ 0.044194173824159216f
#define LOG2E_ 1.4426950408889634f

typedef __nv_bfloat16 bf16;

// ---------------- scratch (device globals) ----------------
__device__ bf16 g_t[(size_t)B_ * S_ * C_];
__device__ bf16 g_q[(size_t)B_ * S_ * C_];
__device__ bf16 g_k[(size_t)B_ * S_ * C_];
__device__ bf16 g_v[(size_t)B_ * S_ * C_];
__device__ bf16 g_o[(size_t)B_ * S_ * C_];
__device__ bf16 g_wb[4 * 16384];   // wq, wk, wv, wo in bf16

// ---------------- helpers ----------------
__device__ __forceinline__ unsigned pack2(float a, float b) {
    __nv_bfloat162 h = __floats2bfloat162_rn(a, b);
    return *reinterpret_cast<unsigned*>(&h);
}
__device__ __forceinline__ float ex2(float x) {
    float r; asm("ex2.approx.ftz.f32 %0, %1;" : "=f"(r) : "f"(x)); return r;
}
__device__ __forceinline__ void mma_bf16(float* d, const unsigned* a, unsigned b0, unsigned b1) {
    asm volatile(
        "mma.sync.aligned.m16n8k16.row.col.f32.bf16.bf16.f32 "
        "{%0,%1,%2,%3}, {%4,%5,%6,%7}, {%8,%9}, {%0,%1,%2,%3};\n"
        : "+f"(d[0]), "+f"(d[1]), "+f"(d[2]), "+f"(d[3])
        : "r"(a[0]), "r"(a[1]), "r"(a[2]), "r"(a[3]), "r"(b0), "r"(b1));
}
__device__ __forceinline__ void ldm_x4(unsigned* r, unsigned addr) {
    asm volatile("ldmatrix.sync.aligned.m8n8.x4.shared.b16 {%0,%1,%2,%3}, [%4];"
                 : "=r"(r[0]), "=r"(r[1]), "=r"(r[2]), "=r"(r[3]) : "r"(addr));
}
__device__ __forceinline__ void ldm_x4t(unsigned* r, unsigned addr) {
    asm volatile("ldmatrix.sync.aligned.m8n8.x4.trans.shared.b16 {%0,%1,%2,%3}, [%4];"
                 : "=r"(r[0]), "=r"(r[1]), "=r"(r[2]), "=r"(r[3]) : "r"(addr));
}
__device__ __forceinline__ unsigned cvta_s(const void* p) {
    return (unsigned)__cvta_generic_to_shared(p);
}
#define CP16(dst, src) asm volatile("cp.async.cg.shared.global [%0], [%1], 16;" :: "r"(dst), "l"(src))
#define CP_COMMIT() asm volatile("cp.async.commit_group;")

#define KV_BYTES 17408     // 64 * 272
#define W_BYTES  34816     // 128 * 272

// ---------------- Kernel 0: convert weights fp32 -> bf16 ----------------
__global__ void convw_kernel(const float* __restrict__ wq, const float* __restrict__ wk,
                             const float* __restrict__ wv, const float* __restrict__ wo,
                             bf16* __restrict__ dst) {
    int i = blockIdx.x * 256 + threadIdx.x;
    const float* s;
    int m = i >> 12;
    if (m == 0) s = wq; else if (m == 1) s = wk; else if (m == 2) s = wv; else s = wo;
    float4 v = reinterpret_cast<const float4*>(s)[i & 4095];
    uint2 u; u.x = pack2(v.x, v.y); u.y = pack2(v.z, v.w);
    reinterpret_cast<uint2*>(dst)[i] = u;
}

// ---------------- Kernel 1: GroupNorm -> t[b,s,c] (bf16) ----------------
__global__ void gn_kernel(const float* __restrict__ x, const float* __restrict__ gw,
                          const float* __restrict__ gb, bf16* __restrict__ t) {
    int b = blockIdx.x >> 5, g = blockIdx.x & 31, tid = threadIdx.x;
    const float* xb = x + ((size_t)b * C_ + g * 4) * S_;
    float vals[4][4], s1 = 0.f, s2 = 0.f;
#pragma unroll
    for (int it = 0; it < 4; ++it) {
        int s = tid + it * 256;
#pragma unroll
        for (int j = 0; j < 4; ++j) {
            float v = xb[(size_t)j * S_ + s];
            vals[it][j] = v; s1 += v; s2 += v * v;
        }
    }
    __shared__ float red0[256], red1[256];
    red0[tid] = s1; red1[tid] = s2;
    __syncthreads();
    for (int off = 128; off > 0; off >>= 1) {
        if (tid < off) { red0[tid] += red0[tid + off]; red1[tid] += red1[tid + off]; }
        __syncthreads();
    }
    __shared__ float mean_s, inv_s;
    if (tid == 0) {
        float m = red0[0] * (1.f / 4096.f);
        float var = red1[0] * (1.f / 4096.f) - m * m;
        mean_s = m; inv_s = rsqrtf(var + EPS);
    }
    __syncthreads();
    float m = mean_s, inv = inv_s, w4[4], b4[4];
#pragma unroll
    for (int j = 0; j < 4; ++j) { w4[j] = gw[g * 4 + j]; b4[j] = gb[g * 4 + j]; }
#pragma unroll
    for (int it = 0; it < 4; ++it) {
        int s = tid + it * 256;
        uint2 u;
        u.x = pack2((vals[it][0] - m) * inv * w4[0] + b4[0], (vals[it][1] - m) * inv * w4[1] + b4[1]);
        u.y = pack2((vals[it][2] - m) * inv * w4[2] + b4[2], (vals[it][3] - m) * inv * w4[3] + b4[3]);
        *reinterpret_cast<uint2*>(&t[((size_t)b * S_ + s) * C_ + g * 4]) = u;
    }
}

// ---------------- Kernel 2: merged QKV GEMM — grid 768, 4 A-tiles per CTA ----------------
// blockIdx.x >> 8 selects {Q,K,V}; & 255 selects the 256-row A strip.
#define GX_SMEM (2 * KV_BYTES + W_BYTES)   // 69632
__global__ __launch_bounds__(128, 2) void qkv_merged_kernel(
    const bf16* __restrict__ A, const bf16* __restrict__ wb,
    const float* __restrict__ bq, const float* __restrict__ bk, const float* __restrict__ bv,
    bf16* __restrict__ q, bf16* __restrict__ k, bf16* __restrict__ v) {
    extern __shared__ char sm[];
    unsigned sb = cvta_s(sm);
    unsigned sw = sb + 2 * KV_BYTES;
    int tid = threadIdx.x, lane = tid & 31, w = tid >> 5;
    int g = lane >> 2, tt = lane & 3, lm = lane >> 3, lr = lane & 7;
    int wsel = blockIdx.x >> 8;
    size_t m0 = (size_t)(blockIdx.x & 255) * 256;

    const bf16* W = wb + (size_t)wsel * 16384;
    const float* bias = (wsel == 0) ? bq : (wsel == 1) ? bk : bv;
    bf16* Out = (wsel == 0) ? q : (wsel == 1) ? k : v;
    float sc = (wsel == 0) ? (SCALE_ * LOG2E_) : 1.f;

    // prologue: W + A tile 0
    for (int i = tid; i < 2048; i += 128) {
        int row = i >> 4, seg = i & 15;
        CP16(sw + row * 272 + seg * 16, W + (size_t)row * 128 + seg * 8);
    }
    for (int i = tid; i < 1024; i += 128) {
        int row = i >> 4, seg = i & 15;
        CP16(sb + row * 272 + seg * 16, A + (m0 + row) * 128 + seg * 8);
    }
    CP_COMMIT();
    asm volatile("cp.async.wait_group 0;");
    __syncthreads();

    int r0 = w * 16 + g;
#pragma unroll 1
    for (int t = 0; t < 4; ++t) {
        unsigned sa = sb + (unsigned)(t & 1) * KV_BYTES;
        if (t < 3) {
            unsigned sa_alt = sb + (unsigned)(1 - (t & 1)) * KV_BYTES;
            const bf16* an = A + (m0 + (size_t)(t + 1) * 64) * 128;
            for (int i = tid; i < 1024; i += 128) {
                int row = i >> 4, seg = i & 15;
                CP16(sa_alt + row * 272 + seg * 16, an + (size_t)row * 128 + seg * 8);
            }
            CP_COMMIT();
        }

        unsigned af[8][4];
#pragma unroll
        for (int kk = 0; kk < 8; ++kk) {
            unsigned addr = sa + (unsigned)(w * 16 + 8 * (lm & 1) + lr) * 272
                          + (unsigned)(kk * 32 + (lm >> 1) * 16);
            ldm_x4(af[kk], addr);
        }

        float acc[16][4];
#pragma unroll
        for (int j = 0; j < 16; ++j)
#pragma unroll
            for (int r = 0; r < 4; ++r) acc[j][r] = 0.f;

#pragma unroll
        for (int kk = 0; kk < 8; ++kk) {
            unsigned kb[8][4];
#pragma unroll
            for (int jp = 0; jp < 8; ++jp) {
                unsigned addr = sw + (unsigned)(16 * jp + 8 * (lm >> 1) + lr) * 272
                              + (unsigned)(kk * 32 + (lm & 1) * 16);
                ldm_x4(kb[jp], addr);
            }
#pragma unroll
            for (int jp = 0; jp < 8; ++jp) {
                mma_bf16(acc[2 * jp], af[kk], kb[jp][0], kb[jp][1]);
                mma_bf16(acc[2 * jp + 1], af[kk], kb[jp][2], kb[jp][3]);
            }
        }

        size_t mrow = m0 + (size_t)t * 64 + r0;
#pragma unroll
        for (int j = 0; j < 16; ++j) {
            int col = 8 * j + 2 * tt;
            float b0f = bias[col], b1f = bias[col + 1];
            *reinterpret_cast<unsigned*>(Out + mrow * 128 + col) =
                pack2((acc[j][0] + b0f) * sc, (acc[j][1] + b1f) * sc);
            *reinterpret_cast<unsigned*>(Out + (mrow + 8) * 128 + col) =
                pack2((acc[j][2] + b0f) * sc, (acc[j][3] + b1f) * sc);
        }

        if (t < 3) {
            asm volatile("cp.async.wait_group 0;");
            __syncthreads();
        }
    }
}

// ---------------- Kernel 3: flash attention (bf16, batched LDSM) ----------------
#define ATT_Q_BYTES 17408
#define ATT_SMEM (ATT_Q_BYTES + 4 * KV_BYTES)   // 87040
__global__ __launch_bounds__(128, 2) void attn_kernel(
    const bf16* __restrict__ Q, const bf16* __restrict__ K,
    const bf16* __restrict__ V, bf16* __restrict__ O) {
    extern __shared__ char sm[];
    unsigned sb = cvta_s(sm);
    int tid = threadIdx.x, lane = tid & 31, w = tid >> 5;
    int g = lane >> 2, tt = lane & 3;
    int lm = lane >> 3, lr = lane & 7;
    int b = blockIdx.x >> 4, qt = blockIdx.x & 15;
    size_t base = (size_t)b * S_ * C_;
    int q0 = qt * 64;
    int r0 = w * 16 + g;

    for (int i = tid; i < 1024; i += 128) {
        int row = i >> 4, seg = i & 15;
        CP16(sb + row * 272 + seg * 16, Q + base + (size_t)(q0 + row) * 128 + seg * 8);
        CP16(sb + ATT_Q_BYTES + row * 272 + seg * 16, K + base + (size_t)row * 128 + seg * 8);
        CP16(sb + ATT_Q_BYTES + KV_BYTES + row * 272 + seg * 16, V + base + (size_t)row * 128 + seg * 8);
    }
    CP_COMMIT();
    asm volatile("cp.async.wait_group 0;");
    __syncthreads();

    unsigned qa[8][4];
#pragma unroll
    for (int kk = 0; kk < 8; ++kk) {
        unsigned addr = sb + (unsigned)(w * 16 + 8 * (lm & 1) + lr) * 272
                      + (unsigned)(kk * 32 + (lm >> 1) * 16);
        ldm_x4(qa[kk], addr);
    }

    float o_[16][4];
#pragma unroll
    for (int j = 0; j < 16; ++j)
#pragma unroll
        for (int r = 0; r < 4; ++r) o_[j][r] = 0.f;
    float l0 = 0.f, l1 = 0.f;

    CP_COMMIT();

    for (int kt = 0; kt < 16; ++kt) {
        int cur = kt & 1;
        asm volatile("cp.async.wait_group 0;");
        __syncthreads();

        if (kt < 15) {
            unsigned kdst = sb + ATT_Q_BYTES + (1 - cur) * (2 * KV_BYTES);
            const bf16* ksrc = K + base + (size_t)(kt + 1) * 64 * 128;
            const bf16* vsrc = V + base + (size_t)(kt + 1) * 64 * 128;
            for (int i = tid; i < 1024; i += 128) {
                int row = i >> 4, seg = i & 15;
                CP16(kdst + row * 272 + seg * 16, ksrc + (size_t)row * 128 + seg * 8);
                CP16(kdst + KV_BYTES + row * 272 + seg * 16, vsrc + (size_t)row * 128 + seg * 8);
            }
        }
        CP_COMMIT();

        unsigned skb = sb + ATT_Q_BYTES + cur * (2 * KV_BYTES);
        unsigned svb = skb + KV_BYTES;

        // ---- S = Q . K^T : batch 4 LDSM, then 8 mma per kk ----
        float s[8][4];
#pragma unroll
        for (int j = 0; j < 8; ++j)
#pragma unroll
            for (int r = 0; r < 4; ++r) s[j][r] = 0.f;
#pragma unroll
        for (int kk = 0; kk < 8; ++kk) {
            unsigned kb[4][4];
#pragma unroll
            for (int jp = 0; jp < 4; ++jp) {
                unsigned addr = skb + (unsigned)(16 * jp + 8 * (lm >> 1) + lr) * 272
                              + (unsigned)(kk * 32 + (lm & 1) * 16);
                ldm_x4(kb[jp], addr);
            }
#pragma unroll
            for (int jp = 0; jp < 4; ++jp) {
                mma_bf16(s[2 * jp], qa[kk], kb[jp][0], kb[jp][1]);
                mma_bf16(s[2 * jp + 1], qa[kk], kb[jp][2], kb[jp][3]);
            }
        }

        unsigned pa[4][4];
#pragma unroll
        for (int j = 0; j < 8; ++j) {
            float p00 = ex2(s[j][0]), p01 = ex2(s[j][1]);
            float p10 = ex2(s[j][2]), p11 = ex2(s[j][3]);
            l0 += p00 + p01; l1 += p10 + p11;
            pa[j >> 1][(j & 1) * 2 + 0] = pack2(p00, p01);
            pa[j >> 1][(j & 1) * 2 + 1] = pack2(p10, p11);
        }

        // ---- O += P . V : batch 8 LDSM.T, then 16 mma per kt2 ----
#pragma unroll
        for (int kt2 = 0; kt2 < 4; ++kt2) {
            unsigned vb[8][4];
#pragma unroll
            for (int jp = 0; jp < 8; ++jp) {
                unsigned addr = svb + (unsigned)(kt2 * 16 + 8 * (lm & 1) + lr) * 272
                              + (unsigned)((2 * jp + (lm >> 1)) * 16);
                ldm_x4t(vb[jp], addr);
            }
#pragma unroll
            for (int jp = 0; jp < 8; ++jp) {
                mma_bf16(o_[2 * jp], pa[kt2], vb[jp][0], vb[jp][1]);
                mma_bf16(o_[2 * jp + 1], pa[kt2], vb[jp][2], vb[jp][3]);
            }
        }
    }

    l0 += __shfl_xor_sync(0xffffffffu, l0, 1);
    l0 += __shfl_xor_sync(0xffffffffu, l0, 2);
    l1 += __shfl_xor_sync(0xffffffffu, l1, 1);
    l1 += __shfl_xor_sync(0xffffffffu, l1, 2);
    float i0 = 1.f / l0, i1 = 1.f / l1;
#pragma unroll
    for (int j = 0; j < 16; ++j) {
        int col = 8 * j + 2 * tt;
        *reinterpret_cast<unsigned*>(O + base + (size_t)(q0 + r0) * 128 + col) =
            pack2(o_[j][0] * i0, o_[j][1] * i0);
        *reinterpret_cast<unsigned*>(O + base + (size_t)(q0 + r0 + 8) * 128 + col) =
            pack2(o_[j][2] * i1, o_[j][3] * i1);
    }
}

// ---------------- Kernel 4: O-proj x4 — resident W, transpose + residual, batched LDSM ----------------
#define OPX_TILE_OFF (2 * KV_BYTES + W_BYTES)            // 69632
#define OPX_SMEM (OPX_TILE_OFF + 128 * 68 * 4)           // 104448
__global__ __launch_bounds__(128, 2) void oprojx4_kernel(
    const bf16* __restrict__ o, const bf16* __restrict__ wo, const float* __restrict__ bo,
    const float* __restrict__ x, float* __restrict__ out) {
    extern __shared__ char sm[];
    unsigned sb = cvta_s(sm);
    unsigned sw = sb + 2 * KV_BYTES;
    float* tile = reinterpret_cast<float*>(sm + OPX_TILE_OFF);
    int tid = threadIdx.x, lane = tid & 31, w = tid >> 5;
    int g = lane >> 2, tt = lane & 3, lm = lane >> 3, lr = lane & 7;
    size_t m0 = (size_t)blockIdx.x * 256;
    int b = blockIdx.x >> 2;
    int sbase = (blockIdx.x & 3) * 256;

    for (int i = tid; i < 2048; i += 128) {
        int row = i >> 4, seg = i & 15;
        CP16(sw + row * 272 + seg * 16, wo + (size_t)row * 128 + seg * 8);
    }
    for (int i = tid; i < 1024; i += 128) {
        int row = i >> 4, seg = i & 15;
        CP16(sb + row * 272 + seg * 16, o + (m0 + row) * 128 + seg * 8);
    }
    CP_COMMIT();
    asm volatile("cp.async.wait_group 0;");
    __syncthreads();

    int r0 = w * 16 + g;
#pragma unroll 1
    for (int t = 0; t < 4; ++t) {
        unsigned sa = sb + (unsigned)(t & 1) * KV_BYTES;
        if (t < 3) {
            unsigned sa_alt = sb + (unsigned)(1 - (t & 1)) * KV_BYTES;
            const bf16* an = o + (m0 + (size_t)(t + 1) * 64) * 128;
            for (int i = tid; i < 1024; i += 128) {
                int row = i >> 4, seg = i & 15;
                CP16(sa_alt + row * 272 + seg * 16, an + (size_t)row * 128 + seg * 8);
            }
            CP_COMMIT();
        }

        unsigned af[8][4];
#pragma unroll
        for (int kk = 0; kk < 8; ++kk) {
            unsigned addr = sa + (unsigned)(w * 16 + 8 * (lm & 1) + lr) * 272
                          + (unsigned)(kk * 32 + (lm >> 1) * 16);
            ldm_x4(af[kk], addr);
        }

        float acc[16][4];
#pragma unroll
        for (int j = 0; j < 16; ++j)
#pragma unroll
            for (int r = 0; r < 4; ++r) acc[j][r] = 0.f;

#pragma unroll
        for (int kk = 0; kk < 8; ++kk) {
            unsigned kb[8][4];
#pragma unroll
            for (int jp = 0; jp < 8; ++jp) {
                unsigned addr = sw + (unsigned)(16 * jp + 8 * (lm >> 1) + lr) * 272
                              + (unsigned)(kk * 32 + (lm & 1) * 16);
                ldm_x4(kb[jp], addr);
            }
#pragma unroll
            for (int jp = 0; jp < 8; ++jp) {
                mma_bf16(acc[2 * jp], af[kk], kb[jp][0], kb[jp][1]);
                mma_bf16(acc[2 * jp + 1], af[kk], kb[jp][2], kb[jp][3]);
            }
        }

#pragma unroll
        for (int j = 0; j < 16; ++j) {
            int col = 8 * j + 2 * tt;
            float b0f = bo[col], b1f = bo[col + 1];
            tile[col * 68 + r0] = acc[j][0] + b0f;
            tile[(col + 1) * 68 + r0] = acc[j][1] + b1f;
            tile[col * 68 + r0 + 8] = acc[j][2] + b0f;
            tile[(col + 1) * 68 + r0 + 8] = acc[j][3] + b1f;
        }
        __syncthreads();

        int s0 = sbase + t * 64;
#pragma unroll
        for (int it = 0; it < 16; ++it) {
            int c = (tid >> 4) + 8 * it;
            int s4 = (tid & 15) * 4;
            float4 vv = *reinterpret_cast<float4*>(&tile[c * 68 + s4]);
            size_t gi = ((size_t)b * C_ + c) * S_ + s0 + s4;
            float4 xr = *reinterpret_cast<const float4*>(&x[gi]);
            vv.x += xr.x; vv.y += xr.y; vv.z += xr.z; vv.w += xr.w;
            *reinterpret_cast<float4*>(&out[gi]) = vv;
        }

        if (t < 3) {
            asm volatile("cp.async.wait_group 0;");
            __syncthreads();
        }
    }
}

// ---------------- launch ----------------
extern "C" void kernel_launch(void* const* d_in, const int* in_sizes, int n_in,
                              void* d_out, int out_size) {
    const float* x    = (const float*)d_in[0];
    const float* gn_w = (const float*)d_in[1];
    const float* gn_b = (const float*)d_in[2];
    const float* wq   = (const float*)d_in[3];
    const float* bq   = (const float*)d_in[4];
    const float* wk   = (const float*)d_in[5];
    const float* bk   = (const float*)d_in[6];
    const float* wv   = (const float*)d_in[7];
    const float* bv   = (const float*)d_in[8];
    const float* wo   = (const float*)d_in[9];
    const float* bo   = (const float*)d_in[10];
    float* out = (float*)d_out;

    bf16 *t, *q, *k, *v, *o, *wb;
    cudaGetSymbolAddress((void**)&t, g_t);
    cudaGetSymbolAddress((void**)&q, g_q);
    cudaGetSymbolAddress((void**)&k, g_k);
    cudaGetSymbolAddress((void**)&v, g_v);
    cudaGetSymbolAddress((void**)&o, g_o);
    cudaGetSymbolAddress((void**)&wb, g_wb);

    cudaFuncSetAttribute(qkv_merged_kernel, cudaFuncAttributeMaxDynamicSharedMemorySize, GX_SMEM);
    cudaFuncSetAttribute(attn_kernel, cudaFuncAttributeMaxDynamicSharedMemorySize, ATT_SMEM);
    cudaFuncSetAttribute(oprojx4_kernel, cudaFuncAttributeMaxDynamicSharedMemorySize, OPX_SMEM);

    convw_kernel<<<64, 256>>>(wq, wk, wv, wo, wb);
    gn_kernel<<<B_ * 32, 256>>>(x, gn_w, gn_b, t);

    qkv_merged_kernel<<<768, 128, GX_SMEM>>>(t, wb, bq, bk, bv, q, k, v);

    attn_kernel<<<1024, 128, ATT_SMEM>>>(q, k, v, o);

    oprojx4_kernel<<<256, 128, OPX_SMEM>>>(o, wb + 3 * 16384, bo, x, out);
}

// round 16
// speedup vs baseline: 1.6336x; 1.0683x over previous
#include <cuda_runtime.h>
#include <cuda_bf16.h>
#include <math.h>

#define B_  64
#define C_  128
#define S_  1024
#define EPS 1e-6f
#define SCALE_ 0.044194173824159216f
#define LOG2E_ 1.4426950408889634f

typedef __nv_bfloat16 bf16;

// ---------------- scratch (device globals) ----------------
__device__ bf16 g_t[(size_t)B_ * S_ * C_];
__device__ bf16 g_q[(size_t)B_ * S_ * C_];
__device__ bf16 g_k[(size_t)B_ * S_ * C_];
__device__ bf16 g_v[(size_t)B_ * S_ * C_];
__device__ bf16 g_wb[4 * 16384];   // wq, wk, wv, wo in bf16

// ---------------- helpers ----------------
__device__ __forceinline__ unsigned pack2(float a, float b) {
    __nv_bfloat162 h = __floats2bfloat162_rn(a, b);
    return *reinterpret_cast<unsigned*>(&h);
}
__device__ __forceinline__ float ex2(float x) {
    float r; asm("ex2.approx.ftz.f32 %0, %1;" : "=f"(r) : "f"(x)); return r;
}
__device__ __forceinline__ void mma_bf16(float* d, const unsigned* a, unsigned b0, unsigned b1) {
    asm volatile(
        "mma.sync.aligned.m16n8k16.row.col.f32.bf16.bf16.f32 "
        "{%0,%1,%2,%3}, {%4,%5,%6,%7}, {%8,%9}, {%0,%1,%2,%3};\n"
        : "+f"(d[0]), "+f"(d[1]), "+f"(d[2]), "+f"(d[3])
        : "r"(a[0]), "r"(a[1]), "r"(a[2]), "r"(a[3]), "r"(b0), "r"(b1));
}
__device__ __forceinline__ void ldm_x4(unsigned* r, unsigned addr) {
    asm volatile("ldmatrix.sync.aligned.m8n8.x4.shared.b16 {%0,%1,%2,%3}, [%4];"
                 : "=r"(r[0]), "=r"(r[1]), "=r"(r[2]), "=r"(r[3]) : "r"(addr));
}
__device__ __forceinline__ void ldm_x4t(unsigned* r, unsigned addr) {
    asm volatile("ldmatrix.sync.aligned.m8n8.x4.trans.shared.b16 {%0,%1,%2,%3}, [%4];"
                 : "=r"(r[0]), "=r"(r[1]), "=r"(r[2]), "=r"(r[3]) : "r"(addr));
}
__device__ __forceinline__ unsigned cvta_s(const void* p) {
    return (unsigned)__cvta_generic_to_shared(p);
}
#define CP16(dst, src) asm volatile("cp.async.cg.shared.global [%0], [%1], 16;" :: "r"(dst), "l"(src))
#define CP_COMMIT() asm volatile("cp.async.commit_group;")

#define KV_BYTES 17408     // 64 * 272
#define W_BYTES  34816     // 128 * 272

// ---------------- Kernel 0: convert weights fp32 -> bf16 ----------------
__global__ void convw_kernel(const float* __restrict__ wq, const float* __restrict__ wk,
                             const float* __restrict__ wv, const float* __restrict__ wo,
                             bf16* __restrict__ dst) {
    int i = blockIdx.x * 256 + threadIdx.x;
    const float* s;
    int m = i >> 12;
    if (m == 0) s = wq; else if (m == 1) s = wk; else if (m == 2) s = wv; else s = wo;
    float4 v = reinterpret_cast<const float4*>(s)[i & 4095];
    uint2 u; u.x = pack2(v.x, v.y); u.y = pack2(v.z, v.w);
    reinterpret_cast<uint2*>(dst)[i] = u;
}

// ---------------- Kernel 1: GroupNorm -> t[b,s,c] (bf16) ----------------
__global__ void gn_kernel(const float* __restrict__ x, const float* __restrict__ gw,
                          const float* __restrict__ gb, bf16* __restrict__ t) {
    int b = blockIdx.x >> 5, g = blockIdx.x & 31, tid = threadIdx.x;
    const float* xb = x + ((size_t)b * C_ + g * 4) * S_;
    float vals[4][4], s1 = 0.f, s2 = 0.f;
#pragma unroll
    for (int it = 0; it < 4; ++it) {
        int s = tid + it * 256;
#pragma unroll
        for (int j = 0; j < 4; ++j) {
            float v = xb[(size_t)j * S_ + s];
            vals[it][j] = v; s1 += v; s2 += v * v;
        }
    }
    __shared__ float red0[256], red1[256];
    red0[tid] = s1; red1[tid] = s2;
    __syncthreads();
    for (int off = 128; off > 0; off >>= 1) {
        if (tid < off) { red0[tid] += red0[tid + off]; red1[tid] += red1[tid + off]; }
        __syncthreads();
    }
    __shared__ float mean_s, inv_s;
    if (tid == 0) {
        float m = red0[0] * (1.f / 4096.f);
        float var = red1[0] * (1.f / 4096.f) - m * m;
        mean_s = m; inv_s = rsqrtf(var + EPS);
    }
    __syncthreads();
    float m = mean_s, inv = inv_s, w4[4], b4[4];
#pragma unroll
    for (int j = 0; j < 4; ++j) { w4[j] = gw[g * 4 + j]; b4[j] = gb[g * 4 + j]; }
#pragma unroll
    for (int it = 0; it < 4; ++it) {
        int s = tid + it * 256;
        uint2 u;
        u.x = pack2((vals[it][0] - m) * inv * w4[0] + b4[0], (vals[it][1] - m) * inv * w4[1] + b4[1]);
        u.y = pack2((vals[it][2] - m) * inv * w4[2] + b4[2], (vals[it][3] - m) * inv * w4[3] + b4[3]);
        *reinterpret_cast<uint2*>(&t[((size_t)b * S_ + s) * C_ + g * 4]) = u;
    }
}

// ---------------- Kernel 2: merged QKV GEMM — grid 768, 4 A-tiles per CTA ----------------
#define GX_SMEM (2 * KV_BYTES + W_BYTES)   // 69632
__global__ __launch_bounds__(128, 2) void qkv_merged_kernel(
    const bf16* __restrict__ A, const bf16* __restrict__ wb,
    const float* __restrict__ bq, const float* __restrict__ bk, const float* __restrict__ bv,
    bf16* __restrict__ q, bf16* __restrict__ k, bf16* __restrict__ v) {
    extern __shared__ char sm[];
    unsigned sb = cvta_s(sm);
    unsigned sw = sb + 2 * KV_BYTES;
    int tid = threadIdx.x, lane = tid & 31, w = tid >> 5;
    int g = lane >> 2, tt = lane & 3, lm = lane >> 3, lr = lane & 7;
    int wsel = blockIdx.x >> 8;
    size_t m0 = (size_t)(blockIdx.x & 255) * 256;

    const bf16* W = wb + (size_t)wsel * 16384;
    const float* bias = (wsel == 0) ? bq : (wsel == 1) ? bk : bv;
    bf16* Out = (wsel == 0) ? q : (wsel == 1) ? k : v;
    float sc = (wsel == 0) ? (SCALE_ * LOG2E_) : 1.f;

    for (int i = tid; i < 2048; i += 128) {
        int row = i >> 4, seg = i & 15;
        CP16(sw + row * 272 + seg * 16, W + (size_t)row * 128 + seg * 8);
    }
    for (int i = tid; i < 1024; i += 128) {
        int row = i >> 4, seg = i & 15;
        CP16(sb + row * 272 + seg * 16, A + (m0 + row) * 128 + seg * 8);
    }
    CP_COMMIT();
    asm volatile("cp.async.wait_group 0;");
    __syncthreads();

    int r0 = w * 16 + g;
#pragma unroll 1
    for (int t = 0; t < 4; ++t) {
        unsigned sa = sb + (unsigned)(t & 1) * KV_BYTES;
        if (t < 3) {
            unsigned sa_alt = sb + (unsigned)(1 - (t & 1)) * KV_BYTES;
            const bf16* an = A + (m0 + (size_t)(t + 1) * 64) * 128;
            for (int i = tid; i < 1024; i += 128) {
                int row = i >> 4, seg = i & 15;
                CP16(sa_alt + row * 272 + seg * 16, an + (size_t)row * 128 + seg * 8);
            }
            CP_COMMIT();
        }

        unsigned af[8][4];
#pragma unroll
        for (int kk = 0; kk < 8; ++kk) {
            unsigned addr = sa + (unsigned)(w * 16 + 8 * (lm & 1) + lr) * 272
                          + (unsigned)(kk * 32 + (lm >> 1) * 16);
            ldm_x4(af[kk], addr);
        }

        float acc[16][4];
#pragma unroll
        for (int j = 0; j < 16; ++j)
#pragma unroll
            for (int r = 0; r < 4; ++r) acc[j][r] = 0.f;

#pragma unroll
        for (int kk = 0; kk < 8; ++kk) {
            unsigned kb[8][4];
#pragma unroll
            for (int jp = 0; jp < 8; ++jp) {
                unsigned addr = sw + (unsigned)(16 * jp + 8 * (lm >> 1) + lr) * 272
                              + (unsigned)(kk * 32 + (lm & 1) * 16);
                ldm_x4(kb[jp], addr);
            }
#pragma unroll
            for (int jp = 0; jp < 8; ++jp) {
                mma_bf16(acc[2 * jp], af[kk], kb[jp][0], kb[jp][1]);
                mma_bf16(acc[2 * jp + 1], af[kk], kb[jp][2], kb[jp][3]);
            }
        }

        size_t mrow = m0 + (size_t)t * 64 + r0;
#pragma unroll
        for (int j = 0; j < 16; ++j) {
            int col = 8 * j + 2 * tt;
            float b0f = bias[col], b1f = bias[col + 1];
            *reinterpret_cast<unsigned*>(Out + mrow * 128 + col) =
                pack2((acc[j][0] + b0f) * sc, (acc[j][1] + b1f) * sc);
            *reinterpret_cast<unsigned*>(Out + (mrow + 8) * 128 + col) =
                pack2((acc[j][2] + b0f) * sc, (acc[j][3] + b1f) * sc);
        }

        if (t < 3) {
            asm volatile("cp.async.wait_group 0;");
            __syncthreads();
        }
    }
}

// ---------------- Kernel 3: flash attention + fused O-proj + transpose + residual ----------------
// smem: [Q 17408][KV buffers 4x17408]; epilogue reuses KV area: wo at +17408 (34816),
// transpose tile at +52224 (34816). Total 87040.
#define ATT_Q_BYTES 17408
#define ATT_SMEM (ATT_Q_BYTES + 4 * KV_BYTES)   // 87040
__global__ __launch_bounds__(128, 2) void attn_fused_kernel(
    const bf16* __restrict__ Q, const bf16* __restrict__ K,
    const bf16* __restrict__ V, const bf16* __restrict__ wo,
    const float* __restrict__ bo, const float* __restrict__ x,
    float* __restrict__ out) {
    extern __shared__ char sm[];
    unsigned sb = cvta_s(sm);
    int tid = threadIdx.x, lane = tid & 31, w = tid >> 5;
    int g = lane >> 2, tt = lane & 3;
    int lm = lane >> 3, lr = lane & 7;
    int b = blockIdx.x >> 4, qt = blockIdx.x & 15;
    size_t base = (size_t)b * S_ * C_;
    int q0 = qt * 64;
    int r0 = w * 16 + g;

    for (int i = tid; i < 1024; i += 128) {
        int row = i >> 4, seg = i & 15;
        CP16(sb + row * 272 + seg * 16, Q + base + (size_t)(q0 + row) * 128 + seg * 8);
        CP16(sb + ATT_Q_BYTES + row * 272 + seg * 16, K + base + (size_t)row * 128 + seg * 8);
        CP16(sb + ATT_Q_BYTES + KV_BYTES + row * 272 + seg * 16, V + base + (size_t)row * 128 + seg * 8);
    }
    CP_COMMIT();
    asm volatile("cp.async.wait_group 0;");
    __syncthreads();

    unsigned qa[8][4];
#pragma unroll
    for (int kk = 0; kk < 8; ++kk) {
        unsigned addr = sb + (unsigned)(w * 16 + 8 * (lm & 1) + lr) * 272
                      + (unsigned)(kk * 32 + (lm >> 1) * 16);
        ldm_x4(qa[kk], addr);
    }

    float o_[16][4];
#pragma unroll
    for (int j = 0; j < 16; ++j)
#pragma unroll
        for (int r = 0; r < 4; ++r) o_[j][r] = 0.f;
    float l0 = 0.f, l1 = 0.f;

    CP_COMMIT();

    for (int kt = 0; kt < 16; ++kt) {
        int cur = kt & 1;
        asm volatile("cp.async.wait_group 0;");
        __syncthreads();

        if (kt < 15) {
            unsigned kdst = sb + ATT_Q_BYTES + (1 - cur) * (2 * KV_BYTES);
            const bf16* ksrc = K + base + (size_t)(kt + 1) * 64 * 128;
            const bf16* vsrc = V + base + (size_t)(kt + 1) * 64 * 128;
            for (int i = tid; i < 1024; i += 128) {
                int row = i >> 4, seg = i & 15;
                CP16(kdst + row * 272 + seg * 16, ksrc + (size_t)row * 128 + seg * 8);
                CP16(kdst + KV_BYTES + row * 272 + seg * 16, vsrc + (size_t)row * 128 + seg * 8);
            }
        }
        CP_COMMIT();

        unsigned skb = sb + ATT_Q_BYTES + cur * (2 * KV_BYTES);
        unsigned svb = skb + KV_BYTES;

        float s[8][4];
#pragma unroll
        for (int j = 0; j < 8; ++j)
#pragma unroll
            for (int r = 0; r < 4; ++r) s[j][r] = 0.f;
#pragma unroll
        for (int kk = 0; kk < 8; ++kk) {
            unsigned kb[4][4];
#pragma unroll
            for (int jp = 0; jp < 4; ++jp) {
                unsigned addr = skb + (unsigned)(16 * jp + 8 * (lm >> 1) + lr) * 272
                              + (unsigned)(kk * 32 + (lm & 1) * 16);
                ldm_x4(kb[jp], addr);
            }
#pragma unroll
            for (int jp = 0; jp < 4; ++jp) {
                mma_bf16(s[2 * jp], qa[kk], kb[jp][0], kb[jp][1]);
                mma_bf16(s[2 * jp + 1], qa[kk], kb[jp][2], kb[jp][3]);
            }
        }

        unsigned pa[4][4];
#pragma unroll
        for (int j = 0; j < 8; ++j) {
            float p00 = ex2(s[j][0]), p01 = ex2(s[j][1]);
            float p10 = ex2(s[j][2]), p11 = ex2(s[j][3]);
            l0 += p00 + p01; l1 += p10 + p11;
            pa[j >> 1][(j & 1) * 2 + 0] = pack2(p00, p01);
            pa[j >> 1][(j & 1) * 2 + 1] = pack2(p10, p11);
        }

#pragma unroll
        for (int kt2 = 0; kt2 < 4; ++kt2) {
            unsigned vb[8][4];
#pragma unroll
            for (int jp = 0; jp < 8; ++jp) {
                unsigned addr = svb + (unsigned)(kt2 * 16 + 8 * (lm & 1) + lr) * 272
                              + (unsigned)((2 * jp + (lm >> 1)) * 16);
                ldm_x4t(vb[jp], addr);
            }
#pragma unroll
            for (int jp = 0; jp < 8; ++jp) {
                mma_bf16(o_[2 * jp], pa[kt2], vb[jp][0], vb[jp][1]);
                mma_bf16(o_[2 * jp + 1], pa[kt2], vb[jp][2], vb[jp][3]);
            }
        }
    }

    // ---- softmax denominators + pack O into A-fragments (bf16) ----
    l0 += __shfl_xor_sync(0xffffffffu, l0, 1);
    l0 += __shfl_xor_sync(0xffffffffu, l0, 2);
    l1 += __shfl_xor_sync(0xffffffffu, l1, 1);
    l1 += __shfl_xor_sync(0xffffffffu, l1, 2);
    float i0 = 1.f / l0, i1 = 1.f / l1;

    unsigned oa[8][4];
#pragma unroll
    for (int kk = 0; kk < 8; ++kk) {
        oa[kk][0] = pack2(o_[2 * kk][0] * i0, o_[2 * kk][1] * i0);
        oa[kk][1] = pack2(o_[2 * kk][2] * i1, o_[2 * kk][3] * i1);
        oa[kk][2] = pack2(o_[2 * kk + 1][0] * i0, o_[2 * kk + 1][1] * i0);
        oa[kk][3] = pack2(o_[2 * kk + 1][2] * i1, o_[2 * kk + 1][3] * i1);
    }

    // ---- load wo into freed KV smem ----
    __syncthreads();   // all warps done with KV buffers
    unsigned swo = sb + ATT_Q_BYTES;
    for (int i = tid; i < 2048; i += 128) {
        int row = i >> 4, seg = i & 15;
        CP16(swo + row * 272 + seg * 16, wo + (size_t)row * 128 + seg * 8);
    }
    CP_COMMIT();
    asm volatile("cp.async.wait_group 0;");
    __syncthreads();

    // ---- O2 = O . wo^T ----
    float acc[16][4];
#pragma unroll
    for (int j = 0; j < 16; ++j)
#pragma unroll
        for (int r = 0; r < 4; ++r) acc[j][r] = 0.f;
#pragma unroll
    for (int kk = 0; kk < 8; ++kk) {
        unsigned kb[8][4];
#pragma unroll
        for (int jp = 0; jp < 8; ++jp) {
            unsigned addr = swo + (unsigned)(16 * jp + 8 * (lm >> 1) + lr) * 272
                          + (unsigned)(kk * 32 + (lm & 1) * 16);
            ldm_x4(kb[jp], addr);
        }
#pragma unroll
        for (int jp = 0; jp < 8; ++jp) {
            mma_bf16(acc[2 * jp], oa[kk], kb[jp][0], kb[jp][1]);
            mma_bf16(acc[2 * jp + 1], oa[kk], kb[jp][2], kb[jp][3]);
        }
    }

    // ---- bias + transpose via smem tile [128 cols][68-float pitch, 64 rows] ----
    float* tile = reinterpret_cast<float*>(sm + ATT_Q_BYTES + W_BYTES);
#pragma unroll
    for (int j = 0; j < 16; ++j) {
        int col = 8 * j + 2 * tt;
        float b0f = bo[col], b1f = bo[col + 1];
        tile[col * 68 + r0] = acc[j][0] + b0f;
        tile[(col + 1) * 68 + r0] = acc[j][1] + b1f;
        tile[col * 68 + r0 + 8] = acc[j][2] + b0f;
        tile[(col + 1) * 68 + r0 + 8] = acc[j][3] + b1f;
    }
    __syncthreads();

    // ---- residual add + store out[b][c][q0..q0+64) ----
#pragma unroll
    for (int it = 0; it < 16; ++it) {
        int c = (tid >> 4) + 8 * it;
        int s4 = (tid & 15) * 4;
        float4 vv = *reinterpret_cast<float4*>(&tile[c * 68 + s4]);
        size_t gi = ((size_t)b * C_ + c) * S_ + q0 + s4;
        float4 xr = *reinterpret_cast<const float4*>(&x[gi]);
        vv.x += xr.x; vv.y += xr.y; vv.z += xr.z; vv.w += xr.w;
        *reinterpret_cast<float4*>(&out[gi]) = vv;
    }
}

// ---------------- launch ----------------
extern "C" void kernel_launch(void* const* d_in, const int* in_sizes, int n_in,
                              void* d_out, int out_size) {
    const float* x    = (const float*)d_in[0];
    const float* gn_w = (const float*)d_in[1];
    const float* gn_b = (const float*)d_in[2];
    const float* wq   = (const float*)d_in[3];
    const float* bq   = (const float*)d_in[4];
    const float* wk   = (const float*)d_in[5];
    const float* bk   = (const float*)d_in[6];
    const float* wv   = (const float*)d_in[7];
    const float* bv   = (const float*)d_in[8];
    const float* wo   = (const float*)d_in[9];
    const float* bo   = (const float*)d_in[10];
    float* out = (float*)d_out;

    bf16 *t, *q, *k, *v, *wb;
    cudaGetSymbolAddress((void**)&t, g_t);
    cudaGetSymbolAddress((void**)&q, g_q);
    cudaGetSymbolAddress((void**)&k, g_k);
    cudaGetSymbolAddress((void**)&v, g_v);
    cudaGetSymbolAddress((void**)&wb, g_wb);

    cudaFuncSetAttribute(qkv_merged_kernel, cudaFuncAttributeMaxDynamicSharedMemorySize, GX_SMEM);
    cudaFuncSetAttribute(attn_fused_kernel, cudaFuncAttributeMaxDynamicSharedMemorySize, ATT_SMEM);

    convw_kernel<<<64, 256>>>(wq, wk, wv, wo, wb);
    gn_kernel<<<B_ * 32, 256>>>(x, gn_w, gn_b, t);

    qkv_merged_kernel<<<768, 128, GX_SMEM>>>(t, wb, bq, bk, bv, q, k, v);

    attn_fused_kernel<<<1024, 128, ATT_SMEM>>>(q, k, v, wb + 3 * 16384, bo, x, out);
}

// round 17
// speedup vs baseline: 1.6943x; 1.0372x over previous
#include <cuda_runtime.h>
#include <cuda_bf16.h>
#include <math.h>

#define B_  64
#define C_  128
#define S_  1024
#define EPS 1e-6f
#define SCALE_ 0.044194173824159216f
#define LOG2E_ 1.4426950408889634f

typedef __nv_bfloat16 bf16;

// ---------------- scratch (device globals) ----------------
__device__ bf16 g_t[(size_t)B_ * S_ * C_];
__device__ bf16 g_q[(size_t)B_ * S_ * C_];
__device__ bf16 g_k[(size_t)B_ * S_ * C_];
__device__ bf16 g_v[(size_t)B_ * S_ * C_];
__device__ bf16 g_wb[4 * 16384];   // wq, wk, wv, wo in bf16

// ---------------- helpers ----------------
__device__ __forceinline__ unsigned pack2(float a, float b) {
    __nv_bfloat162 h = __floats2bfloat162_rn(a, b);
    return *reinterpret_cast<unsigned*>(&h);
}
__device__ __forceinline__ float ex2(float x) {
    float r; asm("ex2.approx.ftz.f32 %0, %1;" : "=f"(r) : "f"(x)); return r;
}
__device__ __forceinline__ void mma_bf16(float* d, const unsigned* a, unsigned b0, unsigned b1) {
    asm volatile(
        "mma.sync.aligned.m16n8k16.row.col.f32.bf16.bf16.f32 "
        "{%0,%1,%2,%3}, {%4,%5,%6,%7}, {%8,%9}, {%0,%1,%2,%3};\n"
        : "+f"(d[0]), "+f"(d[1]), "+f"(d[2]), "+f"(d[3])
        : "r"(a[0]), "r"(a[1]), "r"(a[2]), "r"(a[3]), "r"(b0), "r"(b1));
}
__device__ __forceinline__ void ldm_x4(unsigned* r, unsigned addr) {
    asm volatile("ldmatrix.sync.aligned.m8n8.x4.shared.b16 {%0,%1,%2,%3}, [%4];"
                 : "=r"(r[0]), "=r"(r[1]), "=r"(r[2]), "=r"(r[3]) : "r"(addr));
}
__device__ __forceinline__ void ldm_x4t(unsigned* r, unsigned addr) {
    asm volatile("ldmatrix.sync.aligned.m8n8.x4.trans.shared.b16 {%0,%1,%2,%3}, [%4];"
                 : "=r"(r[0]), "=r"(r[1]), "=r"(r[2]), "=r"(r[3]) : "r"(addr));
}
__device__ __forceinline__ unsigned cvta_s(const void* p) {
    return (unsigned)__cvta_generic_to_shared(p);
}
#define CP16(dst, src) asm volatile("cp.async.cg.shared.global [%0], [%1], 16;" :: "r"(dst), "l"(src))
#define CP_COMMIT() asm volatile("cp.async.commit_group;")
#define STS32(addr, val) asm volatile("st.shared.b32 [%0], %1;" :: "r"(addr), "r"(val))
#define LDS128(v, addr) \
    asm volatile("ld.shared.v4.u32 {%0,%1,%2,%3}, [%4];" \
                 : "=r"((v).x), "=r"((v).y), "=r"((v).z), "=r"((v).w) : "r"(addr))

#define KV_BYTES 17408     // 64 * 272
#define W_BYTES  34816     // 128 * 272

// ---------------- Kernel 0: convert weights fp32 -> bf16 ----------------
__global__ void convw_kernel(const float* __restrict__ wq, const float* __restrict__ wk,
                             const float* __restrict__ wv, const float* __restrict__ wo,
                             bf16* __restrict__ dst) {
    int i = blockIdx.x * 256 + threadIdx.x;
    const float* s;
    int m = i >> 12;
    if (m == 0) s = wq; else if (m == 1) s = wk; else if (m == 2) s = wv; else s = wo;
    float4 v = reinterpret_cast<const float4*>(s)[i & 4095];
    uint2 u; u.x = pack2(v.x, v.y); u.y = pack2(v.z, v.w);
    reinterpret_cast<uint2*>(dst)[i] = u;
}

// ---------------- Kernel 1: GroupNorm -> t[b,s,c] (bf16) ----------------
__global__ void gn_kernel(const float* __restrict__ x, const float* __restrict__ gw,
                          const float* __restrict__ gb, bf16* __restrict__ t) {
    int b = blockIdx.x >> 5, g = blockIdx.x & 31, tid = threadIdx.x;
    const float* xb = x + ((size_t)b * C_ + g * 4) * S_;
    float vals[4][4], s1 = 0.f, s2 = 0.f;
#pragma unroll
    for (int it = 0; it < 4; ++it) {
        int s = tid + it * 256;
#pragma unroll
        for (int j = 0; j < 4; ++j) {
            float v = xb[(size_t)j * S_ + s];
            vals[it][j] = v; s1 += v; s2 += v * v;
        }
    }
    __shared__ float red0[256], red1[256];
    red0[tid] = s1; red1[tid] = s2;
    __syncthreads();
    for (int off = 128; off > 0; off >>= 1) {
        if (tid < off) { red0[tid] += red0[tid + off]; red1[tid] += red1[tid + off]; }
        __syncthreads();
    }
    __shared__ float mean_s, inv_s;
    if (tid == 0) {
        float m = red0[0] * (1.f / 4096.f);
        float var = red1[0] * (1.f / 4096.f) - m * m;
        mean_s = m; inv_s = rsqrtf(var + EPS);
    }
    __syncthreads();
    float m = mean_s, inv = inv_s, w4[4], b4[4];
#pragma unroll
    for (int j = 0; j < 4; ++j) { w4[j] = gw[g * 4 + j]; b4[j] = gb[g * 4 + j]; }
#pragma unroll
    for (int it = 0; it < 4; ++it) {
        int s = tid + it * 256;
        uint2 u;
        u.x = pack2((vals[it][0] - m) * inv * w4[0] + b4[0], (vals[it][1] - m) * inv * w4[1] + b4[1]);
        u.y = pack2((vals[it][2] - m) * inv * w4[2] + b4[2], (vals[it][3] - m) * inv * w4[3] + b4[3]);
        *reinterpret_cast<uint2*>(&t[((size_t)b * S_ + s) * C_ + g * 4]) = u;
    }
}

// ---------------- Kernel 2: merged QKV GEMM — staged coalesced stores ----------------
// blockIdx.x >> 8 selects {Q,K,V}; & 255 selects the 256-row A strip.
#define GX_STAGE_OFF (2 * KV_BYTES + W_BYTES)   // 69632
#define GX_SMEM (GX_STAGE_OFF + KV_BYTES)       // 87040
__global__ __launch_bounds__(128, 2) void qkv_merged_kernel(
    const bf16* __restrict__ A, const bf16* __restrict__ wb,
    const float* __restrict__ bq, const float* __restrict__ bk, const float* __restrict__ bv,
    bf16* __restrict__ q, bf16* __restrict__ k, bf16* __restrict__ v) {
    extern __shared__ char sm[];
    unsigned sb = cvta_s(sm);
    unsigned sw = sb + 2 * KV_BYTES;
    unsigned sst = sb + GX_STAGE_OFF;
    int tid = threadIdx.x, lane = tid & 31, w = tid >> 5;
    int g = lane >> 2, tt = lane & 3, lm = lane >> 3, lr = lane & 7;
    int wsel = blockIdx.x >> 8;
    size_t m0 = (size_t)(blockIdx.x & 255) * 256;

    const bf16* W = wb + (size_t)wsel * 16384;
    const float* bias = (wsel == 0) ? bq : (wsel == 1) ? bk : bv;
    bf16* Out = (wsel == 0) ? q : (wsel == 1) ? k : v;
    float sc = (wsel == 0) ? (SCALE_ * LOG2E_) : 1.f;

    for (int i = tid; i < 2048; i += 128) {
        int row = i >> 4, seg = i & 15;
        CP16(sw + row * 272 + seg * 16, W + (size_t)row * 128 + seg * 8);
    }
    for (int i = tid; i < 1024; i += 128) {
        int row = i >> 4, seg = i & 15;
        CP16(sb + row * 272 + seg * 16, A + (m0 + row) * 128 + seg * 8);
    }
    CP_COMMIT();
    asm volatile("cp.async.wait_group 0;");
    __syncthreads();

    int r0 = w * 16 + g;
#pragma unroll 1
    for (int t = 0; t < 4; ++t) {
        unsigned sa = sb + (unsigned)(t & 1) * KV_BYTES;
        if (t < 3) {
            unsigned sa_alt = sb + (unsigned)(1 - (t & 1)) * KV_BYTES;
            const bf16* an = A + (m0 + (size_t)(t + 1) * 64) * 128;
            for (int i = tid; i < 1024; i += 128) {
                int row = i >> 4, seg = i & 15;
                CP16(sa_alt + row * 272 + seg * 16, an + (size_t)row * 128 + seg * 8);
            }
            CP_COMMIT();
        }

        unsigned af[8][4];
#pragma unroll
        for (int kk = 0; kk < 8; ++kk) {
            unsigned addr = sa + (unsigned)(w * 16 + 8 * (lm & 1) + lr) * 272
                          + (unsigned)(kk * 32 + (lm >> 1) * 16);
            ldm_x4(af[kk], addr);
        }

        float acc[16][4];
#pragma unroll
        for (int j = 0; j < 16; ++j)
#pragma unroll
            for (int r = 0; r < 4; ++r) acc[j][r] = 0.f;

#pragma unroll
        for (int kk = 0; kk < 8; ++kk) {
            unsigned kb[8][4];
#pragma unroll
            for (int jp = 0; jp < 8; ++jp) {
                unsigned addr = sw + (unsigned)(16 * jp + 8 * (lm >> 1) + lr) * 272
                              + (unsigned)(kk * 32 + (lm & 1) * 16);
                ldm_x4(kb[jp], addr);
            }
#pragma unroll
            for (int jp = 0; jp < 8; ++jp) {
                mma_bf16(acc[2 * jp], af[kk], kb[jp][0], kb[jp][1]);
                mma_bf16(acc[2 * jp + 1], af[kk], kb[jp][2], kb[jp][3]);
            }
        }

        // ---- stage to smem (pitch 272B, conflict-free: bank = 4g + tt + 4j) ----
#pragma unroll
        for (int j = 0; j < 16; ++j) {
            int col = 8 * j + 2 * tt;
            float b0f = bias[col], b1f = bias[col + 1];
            STS32(sst + (unsigned)r0 * 272 + (unsigned)col * 2,
                  pack2((acc[j][0] + b0f) * sc, (acc[j][1] + b1f) * sc));
            STS32(sst + (unsigned)(r0 + 8) * 272 + (unsigned)col * 2,
                  pack2((acc[j][2] + b0f) * sc, (acc[j][3] + b1f) * sc));
        }
        __syncthreads();

        // ---- coalesced copy: 64 rows x 256B; each STG.128 covers 512 contiguous bytes ----
        bf16* gout = Out + (m0 + (size_t)t * 64) * 128;
#pragma unroll
        for (int j2 = 0; j2 < 8; ++j2) {
            int idx = tid + j2 * 128;           // 0..1023
            int row = idx >> 4, inner = idx & 15;
            uint4 val;
            LDS128(val, sst + (unsigned)row * 272 + (unsigned)inner * 16);
            *reinterpret_cast<uint4*>(gout + row * 128 + inner * 8) = val;
        }

        if (t < 3) {
            asm volatile("cp.async.wait_group 0;");
        }
        __syncthreads();   // staging reusable + next A tile ready
    }
}

// ---------------- Kernel 3: flash attention + fused O-proj + transpose + residual ----------------
#define ATT_Q_BYTES 17408
#define ATT_SMEM (ATT_Q_BYTES + 4 * KV_BYTES)   // 87040
__global__ __launch_bounds__(128, 2) void attn_fused_kernel(
    const bf16* __restrict__ Q, const bf16* __restrict__ K,
    const bf16* __restrict__ V, const bf16* __restrict__ wo,
    const float* __restrict__ bo, const float* __restrict__ x,
    float* __restrict__ out) {
    extern __shared__ char sm[];
    unsigned sb = cvta_s(sm);
    int tid = threadIdx.x, lane = tid & 31, w = tid >> 5;
    int g = lane >> 2, tt = lane & 3;
    int lm = lane >> 3, lr = lane & 7;
    int b = blockIdx.x >> 4, qt = blockIdx.x & 15;
    size_t base = (size_t)b * S_ * C_;
    int q0 = qt * 64;
    int r0 = w * 16 + g;

    for (int i = tid; i < 1024; i += 128) {
        int row = i >> 4, seg = i & 15;
        CP16(sb + row * 272 + seg * 16, Q + base + (size_t)(q0 + row) * 128 + seg * 8);
        CP16(sb + ATT_Q_BYTES + row * 272 + seg * 16, K + base + (size_t)row * 128 + seg * 8);
        CP16(sb + ATT_Q_BYTES + KV_BYTES + row * 272 + seg * 16, V + base + (size_t)row * 128 + seg * 8);
    }
    CP_COMMIT();
    asm volatile("cp.async.wait_group 0;");
    __syncthreads();

    unsigned qa[8][4];
#pragma unroll
    for (int kk = 0; kk < 8; ++kk) {
        unsigned addr = sb + (unsigned)(w * 16 + 8 * (lm & 1) + lr) * 272
                      + (unsigned)(kk * 32 + (lm >> 1) * 16);
        ldm_x4(qa[kk], addr);
    }

    float o_[16][4];
#pragma unroll
    for (int j = 0; j < 16; ++j)
#pragma unroll
        for (int r = 0; r < 4; ++r) o_[j][r] = 0.f;
    float l0 = 0.f, l1 = 0.f;

    CP_COMMIT();

    for (int kt = 0; kt < 16; ++kt) {
        int cur = kt & 1;
        asm volatile("cp.async.wait_group 0;");
        __syncthreads();

        if (kt < 15) {
            unsigned kdst = sb + ATT_Q_BYTES + (1 - cur) * (2 * KV_BYTES);
            const bf16* ksrc = K + base + (size_t)(kt + 1) * 64 * 128;
            const bf16* vsrc = V + base + (size_t)(kt + 1) * 64 * 128;
            for (int i = tid; i < 1024; i += 128) {
                int row = i >> 4, seg = i & 15;
                CP16(kdst + row * 272 + seg * 16, ksrc + (size_t)row * 128 + seg * 8);
                CP16(kdst + KV_BYTES + row * 272 + seg * 16, vsrc + (size_t)row * 128 + seg * 8);
            }
        }
        CP_COMMIT();

        unsigned skb = sb + ATT_Q_BYTES + cur * (2 * KV_BYTES);
        unsigned svb = skb + KV_BYTES;

        float s[8][4];
#pragma unroll
        for (int j = 0; j < 8; ++j)
#pragma unroll
            for (int r = 0; r < 4; ++r) s[j][r] = 0.f;
#pragma unroll
        for (int kk = 0; kk < 8; ++kk) {
            unsigned kb[4][4];
#pragma unroll
            for (int jp = 0; jp < 4; ++jp) {
                unsigned addr = skb + (unsigned)(16 * jp + 8 * (lm >> 1) + lr) * 272
                              + (unsigned)(kk * 32 + (lm & 1) * 16);
                ldm_x4(kb[jp], addr);
            }
#pragma unroll
            for (int jp = 0; jp < 4; ++jp) {
                mma_bf16(s[2 * jp], qa[kk], kb[jp][0], kb[jp][1]);
                mma_bf16(s[2 * jp + 1], qa[kk], kb[jp][2], kb[jp][3]);
            }
        }

        unsigned pa[4][4];
#pragma unroll
        for (int j = 0; j < 8; ++j) {
            float p00 = ex2(s[j][0]), p01 = ex2(s[j][1]);
            float p10 = ex2(s[j][2]), p11 = ex2(s[j][3]);
            l0 += p00 + p01; l1 += p10 + p11;
            pa[j >> 1][(j & 1) * 2 + 0] = pack2(p00, p01);
            pa[j >> 1][(j & 1) * 2 + 1] = pack2(p10, p11);
        }

#pragma unroll
        for (int kt2 = 0; kt2 < 4; ++kt2) {
            unsigned vb[8][4];
#pragma unroll
            for (int jp = 0; jp < 8; ++jp) {
                unsigned addr = svb + (unsigned)(kt2 * 16 + 8 * (lm & 1) + lr) * 272
                              + (unsigned)((2 * jp + (lm >> 1)) * 16);
                ldm_x4t(vb[jp], addr);
            }
#pragma unroll
            for (int jp = 0; jp < 8; ++jp) {
                mma_bf16(o_[2 * jp], pa[kt2], vb[jp][0], vb[jp][1]);
                mma_bf16(o_[2 * jp + 1], pa[kt2], vb[jp][2], vb[jp][3]);
            }
        }
    }

    // ---- softmax denominators + pack O into A-fragments (bf16) ----
    l0 += __shfl_xor_sync(0xffffffffu, l0, 1);
    l0 += __shfl_xor_sync(0xffffffffu, l0, 2);
    l1 += __shfl_xor_sync(0xffffffffu, l1, 1);
    l1 += __shfl_xor_sync(0xffffffffu, l1, 2);
    float i0 = 1.f / l0, i1 = 1.f / l1;

    unsigned oa[8][4];
#pragma unroll
    for (int kk = 0; kk < 8; ++kk) {
        oa[kk][0] = pack2(o_[2 * kk][0] * i0, o_[2 * kk][1] * i0);
        oa[kk][1] = pack2(o_[2 * kk][2] * i1, o_[2 * kk][3] * i1);
        oa[kk][2] = pack2(o_[2 * kk + 1][0] * i0, o_[2 * kk + 1][1] * i0);
        oa[kk][3] = pack2(o_[2 * kk + 1][2] * i1, o_[2 * kk + 1][3] * i1);
    }

    // ---- load wo into freed KV smem ----
    __syncthreads();
    unsigned swo = sb + ATT_Q_BYTES;
    for (int i = tid; i < 2048; i += 128) {
        int row = i >> 4, seg = i & 15;
        CP16(swo + row * 272 + seg * 16, wo + (size_t)row * 128 + seg * 8);
    }
    CP_COMMIT();
    asm volatile("cp.async.wait_group 0;");
    __syncthreads();

    // ---- O2 = O . wo^T ----
    float acc[16][4];
#pragma unroll
    for (int j = 0; j < 16; ++j)
#pragma unroll
        for (int r = 0; r < 4; ++r) acc[j][r] = 0.f;
#pragma unroll
    for (int kk = 0; kk < 8; ++kk) {
        unsigned kb[8][4];
#pragma unroll
        for (int jp = 0; jp < 8; ++jp) {
            unsigned addr = swo + (unsigned)(16 * jp + 8 * (lm >> 1) + lr) * 272
                          + (unsigned)(kk * 32 + (lm & 1) * 16);
            ldm_x4(kb[jp], addr);
        }
#pragma unroll
        for (int jp = 0; jp < 8; ++jp) {
            mma_bf16(acc[2 * jp], oa[kk], kb[jp][0], kb[jp][1]);
            mma_bf16(acc[2 * jp + 1], oa[kk], kb[jp][2], kb[jp][3]);
        }
    }

    // ---- bias + transpose via smem tile [128 cols][68-float pitch, 64 rows] ----
    float* tile = reinterpret_cast<float*>(sm + ATT_Q_BYTES + W_BYTES);
#pragma unroll
    for (int j = 0; j < 16; ++j) {
        int col = 8 * j + 2 * tt;
        float b0f = bo[col], b1f = bo[col + 1];
        tile[col * 68 + r0] = acc[j][0] + b0f;
        tile[(col + 1) * 68 + r0] = acc[j][1] + b1f;
        tile[col * 68 + r0 + 8] = acc[j][2] + b0f;
        tile[(col + 1) * 68 + r0 + 8] = acc[j][3] + b1f;
    }
    __syncthreads();

    // ---- residual add + store out[b][c][q0..q0+64) ----
#pragma unroll
    for (int it = 0; it < 16; ++it) {
        int c = (tid >> 4) + 8 * it;
        int s4 = (tid & 15) * 4;
        float4 vv = *reinterpret_cast<float4*>(&tile[c * 68 + s4]);
        size_t gi = ((size_t)b * C_ + c) * S_ + q0 + s4;
        float4 xr = *reinterpret_cast<const float4*>(&x[gi]);
        vv.x += xr.x; vv.y += xr.y; vv.z += xr.z; vv.w += xr.w;
        *reinterpret_cast<float4*>(&out[gi]) = vv;
    }
}

// ---------------- launch ----------------
extern "C" void kernel_launch(void* const* d_in, const int* in_sizes, int n_in,
                              void* d_out, int out_size) {
    const float* x    = (const float*)d_in[0];
    const float* gn_w = (const float*)d_in[1];
    const float* gn_b = (const float*)d_in[2];
    const float* wq   = (const float*)d_in[3];
    const float* bq   = (const float*)d_in[4];
    const float* wk   = (const float*)d_in[5];
    const float* bk   = (const float*)d_in[6];
    const float* wv   = (const float*)d_in[7];
    const float* bv   = (const float*)d_in[8];
    const float* wo   = (const float*)d_in[9];
    const float* bo   = (const float*)d_in[10];
    float* out = (float*)d_out;

    bf16 *t, *q, *k, *v, *wb;
    cudaGetSymbolAddress((void**)&t, g_t);
    cudaGetSymbolAddress((void**)&q, g_q);
    cudaGetSymbolAddress((void**)&k, g_k);
    cudaGetSymbolAddress((void**)&v, g_v);
    cudaGetSymbolAddress((void**)&wb, g_wb);

    cudaFuncSetAttribute(qkv_merged_kernel, cudaFuncAttributeMaxDynamicSharedMemorySize, GX_SMEM);
    cudaFuncSetAttribute(attn_fused_kernel, cudaFuncAttributeMaxDynamicSharedMemorySize, ATT_SMEM);

    convw_kernel<<<64, 256>>>(wq, wk, wv, wo, wb);
    gn_kernel<<<B_ * 32, 256>>>(x, gn_w, gn_b, t);

    qkv_merged_kernel<<<768, 128, GX_SMEM>>>(t, wb, bq, bk, bv, q, k, v);

    attn_fused_kernel<<<1024, 128, ATT_SMEM>>>(q, k, v, wb + 3 * 16384, bo, x, out);
}